// round 3
// baseline (speedup 1.0000x reference)
#include <cuda_runtime.h>
#include <math.h>
#include <stdint.h>

// Problem constants
#define NROWS 32768   // B*H*W
#define CDIM  128
#define KCODES 8192
#define BB 32
#define HH 32
#define WW 32

// Output buffer layout: [loss(1)] [out(B*C*H*W)] [perplexity(1)] [idx(NROWS)]
#define OUT_OFF  1
#define PERP_OFF (1 + NROWS*CDIM)
#define IDX_OFF  (PERP_OFF + 1)

// Scratch (static __device__ — no allocations allowed)
__device__ float g_z[NROWS*CDIM];      // projected inputs [N,C]
__device__ float g_zsq[NROWS];         // row squared norms of z
__device__ float g_esq[KCODES];        // row squared norms of emb
__device__ float g_wt[CDIM*CDIM];      // W_lin transposed: g_wt[c*C + j] = W[j,c]
__device__ int   g_idx[NROWS];         // argmin indices
__device__ float g_part[1024];         // per-block SSE partials
__device__ unsigned int g_hist[KCODES];// code usage histogram

// ---------------------------------------------------------------------------
// cp.async helpers
__device__ __forceinline__ void cpa8(uint32_t dst, const void* src) {
    asm volatile("cp.async.ca.shared.global [%0], [%1], 8;" :: "r"(dst), "l"(src));
}
__device__ __forceinline__ void cpa16(uint32_t dst, const void* src) {
    asm volatile("cp.async.ca.shared.global [%0], [%1], 16;" :: "r"(dst), "l"(src));
}
__device__ __forceinline__ void cpa_commit() {
    asm volatile("cp.async.commit_group;" ::: "memory");
}
template <int N>
__device__ __forceinline__ void cpa_wait() {
    asm volatile("cp.async.wait_group %0;" :: "n"(N) : "memory");
}

// ---------------------------------------------------------------------------
// Prep: transpose W into g_wt, zero histogram
__global__ void k_prep(const float* __restrict__ Wl) {
    int i = blockIdx.x * 256 + threadIdx.x;
    if (i < CDIM*CDIM) {
        int j = i / CDIM, c = i % CDIM;
        g_wt[c*CDIM + j] = Wl[i];
    }
    int h = i - CDIM*CDIM;
    if (h >= 0 && h < KCODES) g_hist[h] = 0u;
}

// Row squared norms of emb: warp per row
__global__ void k_esq(const float* __restrict__ emb) {
    int warp = (blockIdx.x * blockDim.x + threadIdx.x) >> 5;
    int lane = threadIdx.x & 31;
    if (warp >= KCODES) return;
    const float* p = emb + (size_t)warp * CDIM;
    float s = 0.f;
    #pragma unroll
    for (int c = lane; c < CDIM; c += 32) { float v = p[c]; s += v*v; }
    #pragma unroll
    for (int o = 16; o > 0; o >>= 1) s += __shfl_xor_sync(0xffffffffu, s, o);
    if (lane == 0) g_esq[warp] = s;
}

// Row squared norms of z: warp per row
__global__ void k_zsq() {
    int warp = (blockIdx.x * blockDim.x + threadIdx.x) >> 5;
    int lane = threadIdx.x & 31;
    if (warp >= NROWS) return;
    const float* p = g_z + (size_t)warp * CDIM;
    float s = 0.f;
    #pragma unroll
    for (int c = lane; c < CDIM; c += 32) { float v = p[c]; s += v*v; }
    #pragma unroll
    for (int o = 16; o > 0; o >>= 1) s += __shfl_xor_sync(0xffffffffu, s, o);
    if (lane == 0) g_zsq[warp] = s;
}

// ---------------------------------------------------------------------------
// Linear projection: z[n,j] = sum_c x[b,c,h,w] * W[j,c] + b[j]
__global__ void k_linear(const float* __restrict__ x, const float* __restrict__ bl) {
    __shared__ float xs[CDIM*WW];   // xs[c*32 + w]
    int bh = blockIdx.x;
    int b = bh >> 5, h = bh & 31;
    int tid = threadIdx.x;          // 128
    int w = tid & 31, cg = tid >> 5;
    const float* xp = x + ((size_t)(b*CDIM) * HH + h) * WW;  // x[b,0,h,0]
    #pragma unroll
    for (int cc = 0; cc < 32; cc++) {
        int c = cg*32 + cc;
        xs[c*WW + w] = xp[(size_t)c * (HH*WW) + w];
    }
    __syncthreads();

    int j = tid;
    float bj = bl[j];
    float acc[WW];
    #pragma unroll
    for (int ww = 0; ww < WW; ww++) acc[ww] = bj;

    #pragma unroll 4
    for (int c = 0; c < CDIM; c++) {
        float wv = g_wt[c*CDIM + j];
        #pragma unroll
        for (int w4 = 0; w4 < WW/4; w4++) {
            float4 xv = *(const float4*)&xs[c*WW + w4*4];
            acc[w4*4+0] += xv.x * wv;
            acc[w4*4+1] += xv.y * wv;
            acc[w4*4+2] += xv.z * wv;
            acc[w4*4+3] += xv.w * wv;
        }
    }
    int nbase = bh * WW;
    #pragma unroll
    for (int ww = 0; ww < WW; ww++)
        g_z[(size_t)(nbase+ww)*CDIM + j] = acc[ww];
}

// ---------------------------------------------------------------------------
// Fused distance + argmin. Block: 128 rows, loop over K in 128-code tiles.
// 256 threads (16x16), 8x8 micro-tile, packed f32x2 FMA.
// Codebook tiles: row-major with XOR swizzle (word ^= (row&15)<<1),
// cp.async double-buffered.
#define RM 128
#define KN 128
#define NT (KCODES/KN)     // 64 tiles
// smem floats: zs RM*CDIM + es 2*KN*CDIM + ssq 2*KN
#define SMEM_ARGMIN ((RM*CDIM + 2*KN*CDIM + 2*KN) * 4)

__global__ void __launch_bounds__(256, 1) k_argmin(const float* __restrict__ emb) {
    extern __shared__ float sm[];
    float* zs  = sm;                       // RM*CDIM
    float* es  = sm + RM*CDIM;             // 2 * KN*CDIM (swizzled)
    float* ssq = es + 2*KN*CDIM;           // 2 * KN

    int tid = threadIdx.x;
    int tx = tid & 15, ty = tid >> 4;
    int rowbase = blockIdx.x * RM;

    uint32_t zs_a  = (uint32_t)__cvta_generic_to_shared(zs);
    uint32_t es_a  = (uint32_t)__cvta_generic_to_shared(es);
    uint32_t ssq_a = (uint32_t)__cvta_generic_to_shared(ssq);

    // Producer: stage codebook tile kt into buffer bufi (XOR-swizzled rows).
    // i = r*64 + c2 with c2 lane-consecutive -> coalesced float2 gmem reads.
    auto stage = [&](int kt, int bufi) {
        const float* src = emb + (size_t)kt * CDIM;
        uint32_t dbase = es_a + (uint32_t)bufi * (KN*CDIM*4);
        #pragma unroll
        for (int u = 0; u < KN*64/256; u++) {
            int i = u*256 + tid;
            int r = i >> 6, c2 = i & 63;
            uint32_t word = (uint32_t)(r*CDIM) + (uint32_t)((2*c2) ^ ((r & 15) << 1));
            cpa8(dbase + word*4, src + r*CDIM + 2*c2);
        }
        if (tid < KN/4)
            cpa16(ssq_a + (uint32_t)bufi*(KN*4) + tid*16, g_esq + kt + tid*4);
    };

    // Prologue: z tile + tile 0 in group 0
    {
        const float* src = g_z + (size_t)rowbase * CDIM;
        for (int u = 0; u < RM*CDIM/4/256; u++) {
            int i = u*256 + tid;
            cpa16(zs_a + (uint32_t)i*16, src + i*4);
        }
        stage(0, 0);
        cpa_commit();
    }

    float zsqr[8];
    #pragma unroll
    for (int i = 0; i < 8; i++) zsqr[i] = g_zsq[rowbase + ty*8 + i];

    float bestv[8]; int besti[8];
    #pragma unroll
    for (int i = 0; i < 8; i++) { bestv[i] = 3.0e38f; besti[i] = 0; }

    const float* zp = zs + (ty*8) * CDIM;

    for (int t = 0; t < NT; t++) {
        if (t + 1 < NT) {
            stage((t+1)*KN, (t+1) & 1);
            cpa_commit();
            cpa_wait<1>();    // current tile's group done
        } else {
            cpa_wait<0>();
        }
        __syncthreads();

        const float* eb = es + (t & 1) * (KN*CDIM);
        const float* sq = ssq + (t & 1) * KN;

        float esqr[8];
        #pragma unroll
        for (int jj = 0; jj < 8; jj++) esqr[jj] = sq[jj*16 + tx];

        unsigned long long acc[8][8];
        #pragma unroll
        for (int i = 0; i < 8; i++)
            #pragma unroll
            for (int j = 0; j < 8; j++) acc[i][j] = 0ull;

        #pragma unroll 2
        for (int c4 = 0; c4 < CDIM/4; c4++) {
            // af: LDS.128, contiguous, broadcast across tx
            ulonglong2 af[8];
            #pragma unroll
            for (int i = 0; i < 8; i++)
                af[i] = *(const ulonglong2*)(zp + i*CDIM + 4*c4);
            #pragma unroll
            for (int sub = 0; sub < 2; sub++) {
                int c2 = 2*c4 + sub;
                int wsw = (2*c2) ^ (tx << 1);    // swizzled word within row
                unsigned long long bf[8];
                #pragma unroll
                for (int jj = 0; jj < 8; jj++)
                    bf[jj] = *(const unsigned long long*)(eb + (jj*16 + tx)*CDIM + wsw);
                #pragma unroll
                for (int i = 0; i < 8; i++) {
                    unsigned long long a = (sub == 0) ? af[i].x : af[i].y;
                    #pragma unroll
                    for (int jj = 0; jj < 8; jj++)
                        asm("fma.rn.f32x2 %0, %1, %2, %0;"
                            : "+l"(acc[i][jj]) : "l"(a), "l"(bf[jj]));
                }
            }
        }

        // Epilogue: d = (zsq + esq) - 2*dot, rounding order matching reference.
        int kt = t * KN;
        #pragma unroll
        for (int i = 0; i < 8; i++) {
            #pragma unroll
            for (int jj = 0; jj < 8; jj++) {
                float lo = __uint_as_float((unsigned int)(acc[i][jj] & 0xffffffffull));
                float hi = __uint_as_float((unsigned int)(acc[i][jj] >> 32));
                float dot = __fadd_rn(lo, hi);
                float se  = __fadd_rn(zsqr[i], esqr[jj]);
                float d   = __fsub_rn(se, __fmul_rn(2.0f, dot));
                if (d < bestv[i]) { bestv[i] = d; besti[i] = kt + jj*16 + tx; }
            }
        }
        __syncthreads();   // tile fully consumed before buffer reuse
    }

    // Cross-thread merge per row (first-index tie-break like argmin)
    float* rmin = sm;
    int*   ridx = (int*)(sm + RM);
    if (tid < RM) { rmin[tid] = 3.0e38f; ridx[tid] = 0x7fffffff; }
    __syncthreads();
    for (int t = 0; t < 16; t++) {
        if (tx == t) {
            #pragma unroll
            for (int i = 0; i < 8; i++) {
                int lr = ty*8 + i;
                if (bestv[i] < rmin[lr] ||
                    (bestv[i] == rmin[lr] && besti[i] < ridx[lr])) {
                    rmin[lr] = bestv[i]; ridx[lr] = besti[i];
                }
            }
        }
        __syncthreads();
    }
    if (tid < RM) g_idx[rowbase + tid] = ridx[tid];
}

// ---------------------------------------------------------------------------
// Gather + BCHW output + SSE partials + histogram + idx output.
__global__ void k_output(const float* __restrict__ emb, float* __restrict__ dout) {
    __shared__ float se[CDIM*(WW+1)];   // se[c*33 + w]
    __shared__ float sz[CDIM*(WW+1)];
    __shared__ int   sidx[WW];
    __shared__ float sred[8];
    int bh = blockIdx.x;
    int b = bh >> 5, h = bh & 31;
    int nbase = bh * WW;
    int tid = threadIdx.x;   // 256

    if (tid < WW) {
        int id = g_idx[nbase + tid];
        sidx[tid] = id;
        atomicAdd(&g_hist[id], 1u);
        dout[IDX_OFF + nbase + tid] = (float)id;
    }
    __syncthreads();

    for (int e = tid; e < WW*CDIM; e += 256) {
        int w = e >> 7, c = e & 127;     // c consecutive across lanes -> coalesced
        se[c*(WW+1) + w] = emb[(size_t)sidx[w]*CDIM + c];
        sz[c*(WW+1) + w] = g_z[(size_t)(nbase+w)*CDIM + c];
    }
    __syncthreads();

    float lsse = 0.f;
    for (int e = tid; e < CDIM*WW; e += 256) {
        int c = e >> 5, w = e & 31;      // w consecutive across lanes
        float q  = se[c*(WW+1) + w];
        float zz = sz[c*(WW+1) + w];
        float df = q - zz;
        lsse += df*df;
        dout[OUT_OFF + (((size_t)(b*CDIM + c))*HH + h)*WW + w] = q;
    }
    #pragma unroll
    for (int o = 16; o > 0; o >>= 1) lsse += __shfl_xor_sync(0xffffffffu, lsse, o);
    if ((tid & 31) == 0) sred[tid >> 5] = lsse;
    __syncthreads();
    if (tid == 0) {
        float s = 0.f;
        #pragma unroll
        for (int i = 0; i < 8; i++) s += sred[i];
        g_part[bh] = s;
    }
}

// ---------------------------------------------------------------------------
// Final scalars: loss and perplexity
__global__ void k_final(float* __restrict__ dout) {
    __shared__ double sr[256];
    int tid = threadIdx.x;
    double s = 0.0;
    for (int i = tid; i < 1024; i += 256) s += (double)g_part[i];
    sr[tid] = s; __syncthreads();
    for (int o = 128; o > 0; o >>= 1) {
        if (tid < o) sr[tid] += sr[tid + o];
        __syncthreads();
    }
    if (tid == 0) {
        double mse = sr[0] / (double)(NROWS*CDIM);
        dout[0] = (float)(1.25 * mse);   // q_latent + 0.25 * e_latent
    }
    __syncthreads();
    double hs = 0.0;
    for (int k = tid; k < KCODES; k += 256) {
        double p = (double)g_hist[k] / (double)NROWS;
        hs += p * log(p + 1e-10);
    }
    sr[tid] = hs; __syncthreads();
    for (int o = 128; o > 0; o >>= 1) {
        if (tid < o) sr[tid] += sr[tid + o];
        __syncthreads();
    }
    if (tid == 0) dout[PERP_OFF] = (float)exp(-sr[0]);
}

// ---------------------------------------------------------------------------
extern "C" void kernel_launch(void* const* d_in, const int* in_sizes, int n_in,
                              void* d_out, int out_size) {
    const float* x   = (const float*)d_in[0];
    const float* Wl  = (const float*)d_in[1];
    const float* bl  = (const float*)d_in[2];
    const float* emb = (const float*)d_in[3];
    float* dout = (float*)d_out;

    cudaFuncSetAttribute(k_argmin, cudaFuncAttributeMaxDynamicSharedMemorySize, SMEM_ARGMIN);

    k_prep<<<96, 256>>>(Wl);
    k_esq<<<(KCODES*32)/256, 256>>>(emb);
    k_linear<<<BB*HH, 128>>>(x, bl);
    k_zsq<<<(NROWS*32)/256, 256>>>();
    k_argmin<<<NROWS/RM, 256, SMEM_ARGMIN>>>(emb);
    k_output<<<BB*HH, 256>>>(emb, dout);
    k_final<<<1, 256>>>(dout);
}

// round 4
// speedup vs baseline: 2.4342x; 2.4342x over previous
#include <cuda_runtime.h>
#include <cuda_bf16.h>
#include <math.h>
#include <stdint.h>

// Problem constants
#define NROWS 32768   // B*H*W
#define CDIM  128
#define KCODES 8192
#define BB 32
#define HH 32
#define WW 32

#define RM 128        // rows per GEMM block
#define KN 128        // codes per tile
#define NT (KCODES/KN)
#define MARGIN 3.0f
#define CAP 16

// Output buffer layout: [loss(1)] [out(B*C*H*W)] [perplexity(1)] [idx(NROWS)]
#define OUT_OFF  1
#define PERP_OFF (1 + NROWS*CDIM)
#define IDX_OFF  (PERP_OFF + 1)

// Scratch (static __device__ — no allocations allowed)
__device__ __align__(256) float g_z[NROWS*CDIM];        // projected inputs [N,C] fp32
__device__ __align__(256) __nv_bfloat16 g_zbf[NROWS*CDIM];
__device__ __align__(256) __nv_bfloat16 g_ebf[KCODES*CDIM];
__device__ __align__(256) float g_zsq[NROWS];
__device__ __align__(256) float g_esq[KCODES];
__device__ __align__(256) float g_thr[NROWS];           // approx min + margin
__device__ __align__(256) int   g_ccnt[NROWS];          // candidate counts
__device__ __align__(256) int   g_cidx[NROWS*CAP];      // candidate indices
__device__ float g_wt[CDIM*CDIM];      // W transposed
__device__ int   g_idx[NROWS];
__device__ float g_part[1024];
__device__ unsigned int g_hist[KCODES];

// ---------------------------------------------------------------------------
// helpers
__device__ __forceinline__ void cpa16(uint32_t dst, const void* src) {
    asm volatile("cp.async.ca.shared.global [%0], [%1], 16;" :: "r"(dst), "l"(src));
}
__device__ __forceinline__ void cpa_commit() {
    asm volatile("cp.async.commit_group;" ::: "memory");
}
template <int N>
__device__ __forceinline__ void cpa_wait() {
    asm volatile("cp.async.wait_group %0;" :: "n"(N) : "memory");
}
__device__ __forceinline__ void ldsm4(uint32_t* r, uint32_t addr) {
    asm volatile("ldmatrix.sync.aligned.m8n8.x4.shared.b16 {%0,%1,%2,%3},[%4];"
                 : "=r"(r[0]), "=r"(r[1]), "=r"(r[2]), "=r"(r[3]) : "r"(addr));
}
__device__ __forceinline__ void mma16816(float* d, const uint32_t* a, const uint32_t* b) {
    asm("mma.sync.aligned.m16n8k16.row.col.f32.bf16.bf16.f32 "
        "{%0,%1,%2,%3},{%4,%5,%6,%7},{%8,%9},{%0,%1,%2,%3};"
        : "+f"(d[0]), "+f"(d[1]), "+f"(d[2]), "+f"(d[3])
        : "r"(a[0]), "r"(a[1]), "r"(a[2]), "r"(a[3]), "r"(b[0]), "r"(b[1]));
}
// monotone float<->u32 key for atomicMin on floats (incl. negatives)
__device__ __forceinline__ unsigned fkey(float f) {
    int i = __float_as_int(f);
    return (i >= 0) ? ((unsigned)i | 0x80000000u) : (unsigned)(~i);
}
__device__ __forceinline__ float finv(unsigned u) {
    int i = (u & 0x80000000u) ? (int)(u & 0x7fffffffu) : ~(int)u;
    return __int_as_float(i);
}

// ---------------------------------------------------------------------------
__global__ void k_prep(const float* __restrict__ Wl) {
    int i = blockIdx.x * 256 + threadIdx.x;
    if (i < CDIM*CDIM) {
        int j = i / CDIM, c = i % CDIM;
        g_wt[c*CDIM + j] = Wl[i];
    }
    int h = i - CDIM*CDIM;
    if (h >= 0 && h < KCODES) g_hist[h] = 0u;
}

// emb row norms + bf16 conversion. Warp per row, lane holds one float4.
__global__ void k_esq(const float* __restrict__ emb) {
    int warp = (blockIdx.x * blockDim.x + threadIdx.x) >> 5;
    int lane = threadIdx.x & 31;
    if (warp >= KCODES) return;
    float4 v = ((const float4*)(emb + (size_t)warp * CDIM))[lane];
    float s = v.x*v.x + v.y*v.y + v.z*v.z + v.w*v.w;
    #pragma unroll
    for (int o = 16; o > 0; o >>= 1) s += __shfl_xor_sync(0xffffffffu, s, o);
    if (lane == 0) g_esq[warp] = s;
    __nv_bfloat162 p0 = __floats2bfloat162_rn(v.x, v.y);
    __nv_bfloat162 p1 = __floats2bfloat162_rn(v.z, v.w);
    uint2 u; u.x = *(unsigned*)&p0; u.y = *(unsigned*)&p1;
    ((uint2*)g_ebf)[warp*32 + lane] = u;
}

// z row norms + zero candidate counts
__global__ void k_zsq() {
    int warp = (blockIdx.x * blockDim.x + threadIdx.x) >> 5;
    int lane = threadIdx.x & 31;
    if (warp >= NROWS) return;
    float4 v = ((const float4*)(g_z + (size_t)warp * CDIM))[lane];
    float s = v.x*v.x + v.y*v.y + v.z*v.z + v.w*v.w;
    #pragma unroll
    for (int o = 16; o > 0; o >>= 1) s += __shfl_xor_sync(0xffffffffu, s, o);
    if (lane == 0) { g_zsq[warp] = s; g_ccnt[warp] = 0; }
}

// ---------------------------------------------------------------------------
// Linear projection -> g_z (fp32) and g_zbf (bf16)
__global__ void k_linear(const float* __restrict__ x, const float* __restrict__ bl) {
    __shared__ float xs[CDIM*WW];
    int bh = blockIdx.x;
    int b = bh >> 5, h = bh & 31;
    int tid = threadIdx.x;          // 128
    int w = tid & 31, cg = tid >> 5;
    const float* xp = x + ((size_t)(b*CDIM) * HH + h) * WW;
    #pragma unroll
    for (int cc = 0; cc < 32; cc++) {
        int c = cg*32 + cc;
        xs[c*WW + w] = xp[(size_t)c * (HH*WW) + w];
    }
    __syncthreads();

    int j = tid;
    float bj = bl[j];
    float acc[WW];
    #pragma unroll
    for (int ww = 0; ww < WW; ww++) acc[ww] = bj;

    #pragma unroll 4
    for (int c = 0; c < CDIM; c++) {
        float wv = g_wt[c*CDIM + j];
        #pragma unroll
        for (int w4 = 0; w4 < WW/4; w4++) {
            float4 xv = *(const float4*)&xs[c*WW + w4*4];
            acc[w4*4+0] += xv.x * wv;
            acc[w4*4+1] += xv.y * wv;
            acc[w4*4+2] += xv.z * wv;
            acc[w4*4+3] += xv.w * wv;
        }
    }
    int nbase = bh * WW;
    #pragma unroll
    for (int ww = 0; ww < WW; ww++) {
        g_z[(size_t)(nbase+ww)*CDIM + j] = acc[ww];
        g_zbf[(size_t)(nbase+ww)*CDIM + j] = __float2bfloat16_rn(acc[ww]);
    }
}

// ---------------------------------------------------------------------------
// bf16 tensor GEMM over distances.
// PASS 0: per-row approx min -> g_thr = min + MARGIN
// PASS 1: append candidates with d~ <= thr to g_cidx
// Block: 128 rows x K loop (tiles of 128 codes). 256 threads = 8 warps:
// warp_m = wid&1 (64 rows), warp_n = wid>>1 (32 codes).
// smem tiles bf16, 16B-chunk XOR swizzle: chunk' = chunk ^ (row&7).
#define SMEM_GEMM (32768 + 65536 + 1024 + 512)

template<int PASS>
__global__ void __launch_bounds__(256, 1) k_gemm() {
    extern __shared__ char smc[];
    char* zt = smc;                               // 32KB
    char* et = smc + 32768;                       // 2 x 32KB
    float* ssq = (float*)(smc + 98304);           // 2 x 128
    unsigned* samin = (unsigned*)(smc + 99328);   // 128 (PASS 0)
    float* sthr = (float*)(smc + 99328);          // 128 (PASS 1)

    int tid = threadIdx.x, lane = tid & 31, wid = tid >> 5;
    int warp_m = wid & 1, warp_n = wid >> 1;
    int rowbase = blockIdx.x * RM;

    uint32_t zt_a = (uint32_t)__cvta_generic_to_shared(zt);
    uint32_t et_a = (uint32_t)__cvta_generic_to_shared(et);
    uint32_t ssq_a = (uint32_t)__cvta_generic_to_shared(ssq);

    auto stage_e = [&](int t) {
        int buf = t & 1;
        const char* src = (const char*)g_ebf + (size_t)t * KN * 256;
        uint32_t db = et_a + (uint32_t)buf * 32768u;
        #pragma unroll
        for (int u = 0; u < 8; u++) {
            int i = u*256 + tid;
            int r = i >> 4, c = i & 15;
            cpa16(db + (uint32_t)(r*16 + (c ^ (r & 7)))*16u, src + r*256 + c*16);
        }
        if (tid < 32)
            cpa16(ssq_a + (uint32_t)buf*512u + (uint32_t)tid*16u, g_esq + t*KN + tid*4);
    };

    // prologue: z tile + e tile 0
    {
        const char* src = (const char*)g_zbf + (size_t)rowbase * 256;
        #pragma unroll
        for (int u = 0; u < 8; u++) {
            int i = u*256 + tid;
            int r = i >> 4, c = i & 15;
            cpa16(zt_a + (uint32_t)(r*16 + (c ^ (r & 7)))*16u, src + r*256 + c*16);
        }
        stage_e(0);
        cpa_commit();
    }
    if (PASS == 0) { if (tid < 128) samin[tid] = 0xFFFFFFFFu; }
    if (PASS == 1) { if (tid < 128) sthr[tid] = g_thr[rowbase + tid]; }

    // per-lane row slots: slot = mt*2 + half -> row offset in block
    int rows8[8]; float zsq8[8], thr8[8], minv8[8];
    #pragma unroll
    for (int sl = 0; sl < 8; sl++) {
        int mt = sl >> 1, half = sl & 1;
        rows8[sl] = warp_m*64 + mt*16 + (lane >> 2) + half*8;
        zsq8[sl] = g_zsq[rowbase + rows8[sl]];
        minv8[sl] = 3.0e38f;
    }
    __syncthreads();
    if (PASS == 1) {
        #pragma unroll
        for (int sl = 0; sl < 8; sl++) thr8[sl] = sthr[rows8[sl]];
    }

    // ldmatrix lane addressing constants
    int hiA = (lane >> 4) & 1;
    int hiB = (lane >> 3) & 1;
    int am7[4]; uint32_t abase[4];
    #pragma unroll
    for (int mt = 0; mt < 4; mt++) {
        int ar = warp_m*64 + mt*16 + (lane & 15);
        am7[mt] = ar & 7; abase[mt] = zt_a + (uint32_t)ar*256u;
    }
    int bm7[2]; uint32_t bbase[2];
    #pragma unroll
    for (int g = 0; g < 2; g++) {
        int br = warp_n*32 + g*16 + (lane & 7) + ((lane >> 4) << 3);
        bm7[g] = br & 7; bbase[g] = et_a + (uint32_t)br*256u;
    }

    for (int t = 0; t < NT; t++) {
        if (t + 1 < NT) { stage_e(t+1); cpa_commit(); cpa_wait<1>(); }
        else cpa_wait<0>();
        __syncthreads();
        uint32_t ebb = (uint32_t)(t & 1) * 32768u;

        float acc[4][4][4];
        #pragma unroll
        for (int a = 0; a < 4; a++)
            #pragma unroll
            for (int b = 0; b < 4; b++)
                #pragma unroll
                for (int c = 0; c < 4; c++) acc[a][b][c] = 0.f;

        #pragma unroll
        for (int s = 0; s < 8; s++) {
            uint32_t Ar[4][4], Br[2][4];
            #pragma unroll
            for (int mt = 0; mt < 4; mt++) {
                uint32_t ad = abase[mt] + (uint32_t)(((2*s + hiA) ^ am7[mt]) << 4);
                ldsm4(Ar[mt], ad);
            }
            #pragma unroll
            for (int g = 0; g < 2; g++) {
                uint32_t bd = bbase[g] + ebb + (uint32_t)(((2*s + hiB) ^ bm7[g]) << 4);
                ldsm4(Br[g], bd);
            }
            #pragma unroll
            for (int mt = 0; mt < 4; mt++)
                #pragma unroll
                for (int g = 0; g < 2; g++) {
                    mma16816(acc[mt][2*g+0], Ar[mt], &Br[g][0]);
                    mma16816(acc[mt][2*g+1], Ar[mt], &Br[g][2]);
                }
        }

        // epilogue: d~ = (zsq+esq) - 2*dot
        const float* sq = ssq + (t & 1) * 128;
        int kt = t * KN;
        #pragma unroll
        for (int nt = 0; nt < 4; nt++) {
            int cbase = warp_n*32 + nt*8 + (lane & 3)*2;
            float2 es2 = *(const float2*)&sq[cbase];
            #pragma unroll
            for (int mt = 0; mt < 4; mt++) {
                float d0 = fmaf(-2.f, acc[mt][nt][0], zsq8[mt*2+0] + es2.x);
                float d1 = fmaf(-2.f, acc[mt][nt][1], zsq8[mt*2+0] + es2.y);
                float d2 = fmaf(-2.f, acc[mt][nt][2], zsq8[mt*2+1] + es2.x);
                float d3 = fmaf(-2.f, acc[mt][nt][3], zsq8[mt*2+1] + es2.y);
                if (PASS == 0) {
                    minv8[mt*2+0] = fminf(minv8[mt*2+0], fminf(d0, d1));
                    minv8[mt*2+1] = fminf(minv8[mt*2+1], fminf(d2, d3));
                } else {
                    int r0 = rowbase + rows8[mt*2+0];
                    int r1 = rowbase + rows8[mt*2+1];
                    if (d0 <= thr8[mt*2+0]) {
                        int p = atomicAdd(&g_ccnt[r0], 1);
                        if (p < CAP) g_cidx[r0*CAP + p] = kt + cbase;
                    }
                    if (d1 <= thr8[mt*2+0]) {
                        int p = atomicAdd(&g_ccnt[r0], 1);
                        if (p < CAP) g_cidx[r0*CAP + p] = kt + cbase + 1;
                    }
                    if (d2 <= thr8[mt*2+1]) {
                        int p = atomicAdd(&g_ccnt[r1], 1);
                        if (p < CAP) g_cidx[r1*CAP + p] = kt + cbase;
                    }
                    if (d3 <= thr8[mt*2+1]) {
                        int p = atomicAdd(&g_ccnt[r1], 1);
                        if (p < CAP) g_cidx[r1*CAP + p] = kt + cbase + 1;
                    }
                }
            }
        }
        __syncthreads();
    }

    if (PASS == 0) {
        #pragma unroll
        for (int sl = 0; sl < 8; sl++) {
            float v = minv8[sl];
            v = fminf(v, __shfl_xor_sync(0xffffffffu, v, 1));
            v = fminf(v, __shfl_xor_sync(0xffffffffu, v, 2));
            if ((lane & 3) == 0) atomicMin(&samin[rows8[sl]], fkey(v));
        }
        __syncthreads();
        if (tid < 128) g_thr[rowbase + tid] = finv(samin[tid]) + MARGIN;
    }
}

// ---------------------------------------------------------------------------
// Exact fp32 rescore of candidates. Warp per row.
__global__ void k_rescore(const float* __restrict__ emb) {
    int wid = threadIdx.x >> 5, lane = threadIdx.x & 31;
    int row = blockIdx.x * 8 + wid;
    float4 z4 = ((const float4*)(g_z + (size_t)row * CDIM))[lane];
    float zs = g_zsq[row];
    int cnt = g_ccnt[row];
    float best = 3.0e38f; int bidx = 0x7fffffff;
    if (cnt <= CAP) {
        for (int c = 0; c < cnt; c++) {
            int idx = g_cidx[row*CAP + c];
            float4 e4 = ((const float4*)(emb + (size_t)idx * CDIM))[lane];
            float p = fmaf(z4.x, e4.x, fmaf(z4.y, e4.y, fmaf(z4.z, e4.z, z4.w*e4.w)));
            #pragma unroll
            for (int o = 16; o > 0; o >>= 1) p += __shfl_xor_sync(0xffffffffu, p, o);
            float d = __fsub_rn(__fadd_rn(zs, g_esq[idx]), __fmul_rn(2.0f, p));
            if (d < best || (d == best && idx < bidx)) { best = d; bidx = idx; }
        }
    } else {
        for (int idx = 0; idx < KCODES; idx++) {
            float4 e4 = ((const float4*)(emb + (size_t)idx * CDIM))[lane];
            float p = fmaf(z4.x, e4.x, fmaf(z4.y, e4.y, fmaf(z4.z, e4.z, z4.w*e4.w)));
            #pragma unroll
            for (int o = 16; o > 0; o >>= 1) p += __shfl_xor_sync(0xffffffffu, p, o);
            float d = __fsub_rn(__fadd_rn(zs, g_esq[idx]), __fmul_rn(2.0f, p));
            if (d < best) { best = d; bidx = idx; }
        }
    }
    if (lane == 0) g_idx[row] = bidx;
}

// ---------------------------------------------------------------------------
// Gather + BCHW output + SSE partials + histogram + idx output.
__global__ void k_output(const float* __restrict__ emb, float* __restrict__ dout) {
    __shared__ float se[CDIM*(WW+1)];
    __shared__ float sz[CDIM*(WW+1)];
    __shared__ int   sidx[WW];
    __shared__ float sred[8];
    int bh = blockIdx.x;
    int b = bh >> 5, h = bh & 31;
    int nbase = bh * WW;
    int tid = threadIdx.x;   // 256

    if (tid < WW) {
        int id = g_idx[nbase + tid];
        sidx[tid] = id;
        atomicAdd(&g_hist[id], 1u);
        dout[IDX_OFF + nbase + tid] = (float)id;
    }
    __syncthreads();

    for (int e = tid; e < WW*CDIM; e += 256) {
        int w = e >> 7, c = e & 127;
        se[c*(WW+1) + w] = emb[(size_t)sidx[w]*CDIM + c];
        sz[c*(WW+1) + w] = g_z[(size_t)(nbase+w)*CDIM + c];
    }
    __syncthreads();

    float lsse = 0.f;
    for (int e = tid; e < CDIM*WW; e += 256) {
        int c = e >> 5, w = e & 31;
        float q  = se[c*(WW+1) + w];
        float zz = sz[c*(WW+1) + w];
        float df = q - zz;
        lsse += df*df;
        dout[OUT_OFF + (((size_t)(b*CDIM + c))*HH + h)*WW + w] = q;
    }
    #pragma unroll
    for (int o = 16; o > 0; o >>= 1) lsse += __shfl_xor_sync(0xffffffffu, lsse, o);
    if ((tid & 31) == 0) sred[tid >> 5] = lsse;
    __syncthreads();
    if (tid == 0) {
        float s = 0.f;
        #pragma unroll
        for (int i = 0; i < 8; i++) s += sred[i];
        g_part[bh] = s;
    }
}

// ---------------------------------------------------------------------------
__global__ void k_final(float* __restrict__ dout) {
    __shared__ double sr[256];
    int tid = threadIdx.x;
    double s = 0.0;
    for (int i = tid; i < 1024; i += 256) s += (double)g_part[i];
    sr[tid] = s; __syncthreads();
    for (int o = 128; o > 0; o >>= 1) {
        if (tid < o) sr[tid] += sr[tid + o];
        __syncthreads();
    }
    if (tid == 0) {
        double mse = sr[0] / (double)(NROWS*CDIM);
        dout[0] = (float)(1.25 * mse);
    }
    __syncthreads();
    double hs = 0.0;
    for (int k = tid; k < KCODES; k += 256) {
        double p = (double)g_hist[k] / (double)NROWS;
        hs += p * log(p + 1e-10);
    }
    sr[tid] = hs; __syncthreads();
    for (int o = 128; o > 0; o >>= 1) {
        if (tid < o) sr[tid] += sr[tid + o];
        __syncthreads();
    }
    if (tid == 0) dout[PERP_OFF] = (float)exp(-sr[0]);
}

// ---------------------------------------------------------------------------
extern "C" void kernel_launch(void* const* d_in, const int* in_sizes, int n_in,
                              void* d_out, int out_size) {
    const float* x   = (const float*)d_in[0];
    const float* Wl  = (const float*)d_in[1];
    const float* bl  = (const float*)d_in[2];
    const float* emb = (const float*)d_in[3];
    float* dout = (float*)d_out;

    cudaFuncSetAttribute(k_gemm<0>, cudaFuncAttributeMaxDynamicSharedMemorySize, SMEM_GEMM);
    cudaFuncSetAttribute(k_gemm<1>, cudaFuncAttributeMaxDynamicSharedMemorySize, SMEM_GEMM);

    k_prep<<<96, 256>>>(Wl);
    k_esq<<<(KCODES*32)/256, 256>>>(emb);
    k_linear<<<BB*HH, 128>>>(x, bl);
    k_zsq<<<(NROWS*32)/256, 256>>>();
    k_gemm<0><<<NROWS/RM, 256, SMEM_GEMM>>>();
    k_gemm<1><<<NROWS/RM, 256, SMEM_GEMM>>>();
    k_rescore<<<NROWS/8, 256>>>(emb);
    k_output<<<BB*HH, 256>>>(emb, dout);
    k_final<<<1, 256>>>(dout);
}

// round 5
// speedup vs baseline: 2.5884x; 1.0633x over previous
#include <cuda_runtime.h>
#include <cuda_bf16.h>
#include <math.h>
#include <stdint.h>

// Problem constants
#define NROWS 32768   // B*H*W
#define CDIM  128
#define KCODES 8192
#define BB 32
#define HH 32
#define WW 32

#define RM 128        // rows per GEMM block
#define KN 128        // codes per tile
#define NT (KCODES/KN)
#define MARGIN 3.0f
#define CAP 32

// Output buffer layout: [loss(1)] [out(B*C*H*W)] [perplexity(1)] [idx(NROWS)]
#define OUT_OFF  1
#define PERP_OFF (1 + NROWS*CDIM)
#define IDX_OFF  (PERP_OFF + 1)

// Scratch (static __device__ — no allocations allowed)
__device__ __align__(256) float g_z[NROWS*CDIM];        // projected inputs [N,C] fp32
__device__ __align__(256) __nv_bfloat16 g_zbf[NROWS*CDIM];
__device__ __align__(256) __nv_bfloat16 g_ebf[KCODES*CDIM];
__device__ __align__(256) float g_zsq[NROWS];
__device__ __align__(256) float g_esq[KCODES];
__device__ __align__(256) int   g_ccnt[NROWS];          // candidate counts
__device__ __align__(256) int   g_cidx[NROWS*CAP];      // candidate indices
__device__ float g_wt[CDIM*CDIM];      // W transposed
__device__ int   g_idx[NROWS];
__device__ float g_part[1024];
__device__ unsigned int g_hist[KCODES];

// ---------------------------------------------------------------------------
// helpers
__device__ __forceinline__ void cpa16(uint32_t dst, const void* src) {
    asm volatile("cp.async.ca.shared.global [%0], [%1], 16;" :: "r"(dst), "l"(src));
}
__device__ __forceinline__ void cpa_commit() {
    asm volatile("cp.async.commit_group;" ::: "memory");
}
template <int N>
__device__ __forceinline__ void cpa_wait() {
    asm volatile("cp.async.wait_group %0;" :: "n"(N) : "memory");
}
__device__ __forceinline__ void ldsm4(uint32_t* r, uint32_t addr) {
    asm volatile("ldmatrix.sync.aligned.m8n8.x4.shared.b16 {%0,%1,%2,%3},[%4];"
                 : "=r"(r[0]), "=r"(r[1]), "=r"(r[2]), "=r"(r[3]) : "r"(addr));
}
__device__ __forceinline__ void mma16816(float* d, const uint32_t* a, const uint32_t* b) {
    asm("mma.sync.aligned.m16n8k16.row.col.f32.bf16.bf16.f32 "
        "{%0,%1,%2,%3},{%4,%5,%6,%7},{%8,%9},{%0,%1,%2,%3};"
        : "+f"(d[0]), "+f"(d[1]), "+f"(d[2]), "+f"(d[3])
        : "r"(a[0]), "r"(a[1]), "r"(a[2]), "r"(a[3]), "r"(b[0]), "r"(b[1]));
}
// monotone float<->u32 key for atomicMin on floats (incl. negatives)
__device__ __forceinline__ unsigned fkey(float f) {
    int i = __float_as_int(f);
    return (i >= 0) ? ((unsigned)i | 0x80000000u) : (unsigned)(~i);
}
__device__ __forceinline__ float finv(unsigned u) {
    int i = (u & 0x80000000u) ? (int)(u & 0x7fffffffu) : ~(int)u;
    return __int_as_float(i);
}

// ---------------------------------------------------------------------------
__global__ void k_prep(const float* __restrict__ Wl) {
    int i = blockIdx.x * 256 + threadIdx.x;
    if (i < CDIM*CDIM) {
        int j = i / CDIM, c = i % CDIM;
        g_wt[c*CDIM + j] = Wl[i];
    }
    int h = i - CDIM*CDIM;
    if (h >= 0 && h < KCODES) g_hist[h] = 0u;
}

// emb row norms + bf16 conversion. Warp per row, lane holds one float4.
__global__ void k_esq(const float* __restrict__ emb) {
    int warp = (blockIdx.x * blockDim.x + threadIdx.x) >> 5;
    int lane = threadIdx.x & 31;
    if (warp >= KCODES) return;
    float4 v = ((const float4*)(emb + (size_t)warp * CDIM))[lane];
    float s = v.x*v.x + v.y*v.y + v.z*v.z + v.w*v.w;
    #pragma unroll
    for (int o = 16; o > 0; o >>= 1) s += __shfl_xor_sync(0xffffffffu, s, o);
    if (lane == 0) g_esq[warp] = s;
    __nv_bfloat162 p0 = __floats2bfloat162_rn(v.x, v.y);
    __nv_bfloat162 p1 = __floats2bfloat162_rn(v.z, v.w);
    uint2 u; u.x = *(unsigned*)&p0; u.y = *(unsigned*)&p1;
    ((uint2*)g_ebf)[warp*32 + lane] = u;
}

// z row norms + zero candidate counts
__global__ void k_zsq() {
    int warp = (blockIdx.x * blockDim.x + threadIdx.x) >> 5;
    int lane = threadIdx.x & 31;
    if (warp >= NROWS) return;
    float4 v = ((const float4*)(g_z + (size_t)warp * CDIM))[lane];
    float s = v.x*v.x + v.y*v.y + v.z*v.z + v.w*v.w;
    #pragma unroll
    for (int o = 16; o > 0; o >>= 1) s += __shfl_xor_sync(0xffffffffu, s, o);
    if (lane == 0) { g_zsq[warp] = s; g_ccnt[warp] = 0; }
}

// ---------------------------------------------------------------------------
// Linear projection -> g_z (fp32) and g_zbf (bf16)
__global__ void k_linear(const float* __restrict__ x, const float* __restrict__ bl) {
    __shared__ float xs[CDIM*WW];
    int bh = blockIdx.x;
    int b = bh >> 5, h = bh & 31;
    int tid = threadIdx.x;          // 128
    int w = tid & 31, cg = tid >> 5;
    const float* xp = x + ((size_t)(b*CDIM) * HH + h) * WW;
    #pragma unroll
    for (int cc = 0; cc < 32; cc++) {
        int c = cg*32 + cc;
        xs[c*WW + w] = xp[(size_t)c * (HH*WW) + w];
    }
    __syncthreads();

    int j = tid;
    float bj = bl[j];
    float acc[WW];
    #pragma unroll
    for (int ww = 0; ww < WW; ww++) acc[ww] = bj;

    #pragma unroll 4
    for (int c = 0; c < CDIM; c++) {
        float wv = g_wt[c*CDIM + j];
        #pragma unroll
        for (int w4 = 0; w4 < WW/4; w4++) {
            float4 xv = *(const float4*)&xs[c*WW + w4*4];
            acc[w4*4+0] += xv.x * wv;
            acc[w4*4+1] += xv.y * wv;
            acc[w4*4+2] += xv.z * wv;
            acc[w4*4+3] += xv.w * wv;
        }
    }
    int nbase = bh * WW;
    #pragma unroll
    for (int ww = 0; ww < WW; ww++) {
        g_z[(size_t)(nbase+ww)*CDIM + j] = acc[ww];
        g_zbf[(size_t)(nbase+ww)*CDIM + j] = __float2bfloat16_rn(acc[ww]);
    }
}

// ---------------------------------------------------------------------------
// Single-pass bf16 tensor GEMM + running-min threshold + candidate collection.
// Block: 128 rows x K loop (tiles of 128 codes). 256 threads = 8 warps:
// warp_m = wid&1 (64 rows), warp_n = wid>>1 (32 codes).
// smem tiles bf16, 16B-chunk XOR swizzle: chunk' = chunk ^ (row&7).
// Per tile: compute d~, merge per-row tile min into samin (monotone running
// min), sync, collect all codes with d~ <= running_min + MARGIN. Running min
// >= final min always -> collected set is a superset of the exact-safe set.
#define SMEM_GEMM (32768 + 65536 + 1024 + 512)

__global__ void __launch_bounds__(256, 1) k_gemm() {
    extern __shared__ char smc[];
    char* zt = smc;                               // 32KB
    char* et = smc + 32768;                       // 2 x 32KB
    float* ssq = (float*)(smc + 98304);           // 2 x 128
    unsigned* samin = (unsigned*)(smc + 99328);   // 128 running row-min (fkey)

    int tid = threadIdx.x, lane = tid & 31, wid = tid >> 5;
    int warp_m = wid & 1, warp_n = wid >> 1;
    int rowbase = blockIdx.x * RM;

    uint32_t zt_a = (uint32_t)__cvta_generic_to_shared(zt);
    uint32_t et_a = (uint32_t)__cvta_generic_to_shared(et);
    uint32_t ssq_a = (uint32_t)__cvta_generic_to_shared(ssq);

    auto stage_e = [&](int t) {
        int buf = t & 1;
        const char* src = (const char*)g_ebf + (size_t)t * KN * 256;
        uint32_t db = et_a + (uint32_t)buf * 32768u;
        #pragma unroll
        for (int u = 0; u < 8; u++) {
            int i = u*256 + tid;
            int r = i >> 4, c = i & 15;
            cpa16(db + (uint32_t)(r*16 + (c ^ (r & 7)))*16u, src + r*256 + c*16);
        }
        if (tid < 32)
            cpa16(ssq_a + (uint32_t)buf*512u + (uint32_t)tid*16u, g_esq + t*KN + tid*4);
    };

    // prologue: z tile + e tile 0
    {
        const char* src = (const char*)g_zbf + (size_t)rowbase * 256;
        #pragma unroll
        for (int u = 0; u < 8; u++) {
            int i = u*256 + tid;
            int r = i >> 4, c = i & 15;
            cpa16(zt_a + (uint32_t)(r*16 + (c ^ (r & 7)))*16u, src + r*256 + c*16);
        }
        stage_e(0);
        cpa_commit();
    }
    if (tid < 128) samin[tid] = 0xFFFFFFFFu;

    // per-lane row slots: slot = mt*2 + half -> row offset in block
    int rows8[8]; float zsq8[8];
    #pragma unroll
    for (int sl = 0; sl < 8; sl++) {
        int mt = sl >> 1, half = sl & 1;
        rows8[sl] = warp_m*64 + mt*16 + (lane >> 2) + half*8;
        zsq8[sl] = g_zsq[rowbase + rows8[sl]];
    }

    // ldmatrix lane addressing constants
    int hiA = (lane >> 4) & 1;
    int hiB = (lane >> 3) & 1;
    int am7[4]; uint32_t abase[4];
    #pragma unroll
    for (int mt = 0; mt < 4; mt++) {
        int ar = warp_m*64 + mt*16 + (lane & 15);
        am7[mt] = ar & 7; abase[mt] = zt_a + (uint32_t)ar*256u;
    }
    int bm7[2]; uint32_t bbase[2];
    #pragma unroll
    for (int g = 0; g < 2; g++) {
        int br = warp_n*32 + g*16 + (lane & 7) + ((lane >> 4) << 3);
        bm7[g] = br & 7; bbase[g] = et_a + (uint32_t)br*256u;
    }

    for (int t = 0; t < NT; t++) {
        if (t + 1 < NT) { stage_e(t+1); cpa_commit(); cpa_wait<1>(); }
        else cpa_wait<0>();
        __syncthreads();   // tile ready (also covers samin init at t=0)
        uint32_t ebb = (uint32_t)(t & 1) * 32768u;

        float acc[4][4][4];
        #pragma unroll
        for (int a = 0; a < 4; a++)
            #pragma unroll
            for (int b = 0; b < 4; b++)
                #pragma unroll
                for (int c = 0; c < 4; c++) acc[a][b][c] = 0.f;

        #pragma unroll
        for (int s = 0; s < 8; s++) {
            uint32_t Ar[4][4], Br[2][4];
            #pragma unroll
            for (int mt = 0; mt < 4; mt++) {
                uint32_t ad = abase[mt] + (uint32_t)(((2*s + hiA) ^ am7[mt]) << 4);
                ldsm4(Ar[mt], ad);
            }
            #pragma unroll
            for (int g = 0; g < 2; g++) {
                uint32_t bd = bbase[g] + ebb + (uint32_t)(((2*s + hiB) ^ bm7[g]) << 4);
                ldsm4(Br[g], bd);
            }
            #pragma unroll
            for (int mt = 0; mt < 4; mt++)
                #pragma unroll
                for (int g = 0; g < 2; g++) {
                    mma16816(acc[mt][2*g+0], Ar[mt], &Br[g][0]);
                    mma16816(acc[mt][2*g+1], Ar[mt], &Br[g][2]);
                }
        }

        // epilogue part 1: d~ = (zsq+esq) - 2*dot (in place), per-slot tile min
        const float* sq = ssq + (t & 1) * 128;
        float tmin[8];
        #pragma unroll
        for (int sl = 0; sl < 8; sl++) tmin[sl] = 3.0e38f;
        #pragma unroll
        for (int nt = 0; nt < 4; nt++) {
            int cbase = warp_n*32 + nt*8 + (lane & 3)*2;
            float2 es2 = *(const float2*)&sq[cbase];
            #pragma unroll
            for (int mt = 0; mt < 4; mt++) {
                float d0 = fmaf(-2.f, acc[mt][nt][0], zsq8[mt*2+0] + es2.x);
                float d1 = fmaf(-2.f, acc[mt][nt][1], zsq8[mt*2+0] + es2.y);
                float d2 = fmaf(-2.f, acc[mt][nt][2], zsq8[mt*2+1] + es2.x);
                float d3 = fmaf(-2.f, acc[mt][nt][3], zsq8[mt*2+1] + es2.y);
                acc[mt][nt][0] = d0; acc[mt][nt][1] = d1;
                acc[mt][nt][2] = d2; acc[mt][nt][3] = d3;
                tmin[mt*2+0] = fminf(tmin[mt*2+0], fminf(d0, d1));
                tmin[mt*2+1] = fminf(tmin[mt*2+1], fminf(d2, d3));
            }
        }
        // merge tile min into running row min (lanes 0..3 of each row group)
        #pragma unroll
        for (int sl = 0; sl < 8; sl++) {
            float v = tmin[sl];
            v = fminf(v, __shfl_xor_sync(0xffffffffu, v, 1));
            v = fminf(v, __shfl_xor_sync(0xffffffffu, v, 2));
            if ((lane & 3) == 0) atomicMin(&samin[rows8[sl]], fkey(v));
        }
        __syncthreads();   // all warps' mins merged -> thr includes tile t

        // epilogue part 2: collect candidates under running threshold
        float thr8[8];
        #pragma unroll
        for (int sl = 0; sl < 8; sl++) thr8[sl] = finv(samin[rows8[sl]]) + MARGIN;
        int kt = t * KN;
        #pragma unroll
        for (int nt = 0; nt < 4; nt++) {
            int cbase = warp_n*32 + nt*8 + (lane & 3)*2;
            #pragma unroll
            for (int mt = 0; mt < 4; mt++) {
                int r0 = rowbase + rows8[mt*2+0];
                int r1 = rowbase + rows8[mt*2+1];
                if (acc[mt][nt][0] <= thr8[mt*2+0]) {
                    int p = atomicAdd(&g_ccnt[r0], 1);
                    if (p < CAP) g_cidx[r0*CAP + p] = kt + cbase;
                }
                if (acc[mt][nt][1] <= thr8[mt*2+0]) {
                    int p = atomicAdd(&g_ccnt[r0], 1);
                    if (p < CAP) g_cidx[r0*CAP + p] = kt + cbase + 1;
                }
                if (acc[mt][nt][2] <= thr8[mt*2+1]) {
                    int p = atomicAdd(&g_ccnt[r1], 1);
                    if (p < CAP) g_cidx[r1*CAP + p] = kt + cbase;
                }
                if (acc[mt][nt][3] <= thr8[mt*2+1]) {
                    int p = atomicAdd(&g_ccnt[r1], 1);
                    if (p < CAP) g_cidx[r1*CAP + p] = kt + cbase + 1;
                }
            }
        }
        __syncthreads();   // tile fully consumed before buffer reuse
    }
}

// ---------------------------------------------------------------------------
// Exact fp32 rescore of candidates. Warp per row.
__global__ void k_rescore(const float* __restrict__ emb) {
    int wid = threadIdx.x >> 5, lane = threadIdx.x & 31;
    int row = blockIdx.x * 8 + wid;
    float4 z4 = ((const float4*)(g_z + (size_t)row * CDIM))[lane];
    float zs = g_zsq[row];
    int cnt = g_ccnt[row];
    float best = 3.0e38f; int bidx = 0x7fffffff;
    if (cnt <= CAP) {
        for (int c = 0; c < cnt; c++) {
            int idx = g_cidx[row*CAP + c];
            float4 e4 = ((const float4*)(emb + (size_t)idx * CDIM))[lane];
            float p = fmaf(z4.x, e4.x, fmaf(z4.y, e4.y, fmaf(z4.z, e4.z, z4.w*e4.w)));
            #pragma unroll
            for (int o = 16; o > 0; o >>= 1) p += __shfl_xor_sync(0xffffffffu, p, o);
            float d = __fsub_rn(__fadd_rn(zs, g_esq[idx]), __fmul_rn(2.0f, p));
            if (d < best || (d == best && idx < bidx)) { best = d; bidx = idx; }
        }
    } else {
        for (int idx = 0; idx < KCODES; idx++) {
            float4 e4 = ((const float4*)(emb + (size_t)idx * CDIM))[lane];
            float p = fmaf(z4.x, e4.x, fmaf(z4.y, e4.y, fmaf(z4.z, e4.z, z4.w*e4.w)));
            #pragma unroll
            for (int o = 16; o > 0; o >>= 1) p += __shfl_xor_sync(0xffffffffu, p, o);
            float d = __fsub_rn(__fadd_rn(zs, g_esq[idx]), __fmul_rn(2.0f, p));
            if (d < best) { best = d; bidx = idx; }
        }
    }
    if (lane == 0) g_idx[row] = bidx;
}

// ---------------------------------------------------------------------------
// Gather + BCHW output + SSE partials + histogram + idx output.
__global__ void k_output(const float* __restrict__ emb, float* __restrict__ dout) {
    __shared__ float se[CDIM*(WW+1)];
    __shared__ float sz[CDIM*(WW+1)];
    __shared__ int   sidx[WW];
    __shared__ float sred[8];
    int bh = blockIdx.x;
    int b = bh >> 5, h = bh & 31;
    int nbase = bh * WW;
    int tid = threadIdx.x;   // 256

    if (tid < WW) {
        int id = g_idx[nbase + tid];
        sidx[tid] = id;
        atomicAdd(&g_hist[id], 1u);
        dout[IDX_OFF + nbase + tid] = (float)id;
    }
    __syncthreads();

    for (int e = tid; e < WW*CDIM; e += 256) {
        int w = e >> 7, c = e & 127;
        se[c*(WW+1) + w] = emb[(size_t)sidx[w]*CDIM + c];
        sz[c*(WW+1) + w] = g_z[(size_t)(nbase+w)*CDIM + c];
    }
    __syncthreads();

    float lsse = 0.f;
    for (int e = tid; e < CDIM*WW; e += 256) {
        int c = e >> 5, w = e & 31;
        float q  = se[c*(WW+1) + w];
        float zz = sz[c*(WW+1) + w];
        float df = q - zz;
        lsse += df*df;
        dout[OUT_OFF + (((size_t)(b*CDIM + c))*HH + h)*WW + w] = q;
    }
    #pragma unroll
    for (int o = 16; o > 0; o >>= 1) lsse += __shfl_xor_sync(0xffffffffu, lsse, o);
    if ((tid & 31) == 0) sred[tid >> 5] = lsse;
    __syncthreads();
    if (tid == 0) {
        float s = 0.f;
        #pragma unroll
        for (int i = 0; i < 8; i++) s += sred[i];
        g_part[bh] = s;
    }
}

// ---------------------------------------------------------------------------
__global__ void k_final(float* __restrict__ dout) {
    __shared__ double sr[256];
    int tid = threadIdx.x;
    double s = 0.0;
    for (int i = tid; i < 1024; i += 256) s += (double)g_part[i];
    sr[tid] = s; __syncthreads();
    for (int o = 128; o > 0; o >>= 1) {
        if (tid < o) sr[tid] += sr[tid + o];
        __syncthreads();
    }
    if (tid == 0) {
        double mse = sr[0] / (double)(NROWS*CDIM);
        dout[0] = (float)(1.25 * mse);
    }
    __syncthreads();
    double hs = 0.0;
    for (int k = tid; k < KCODES; k += 256) {
        double p = (double)g_hist[k] / (double)NROWS;
        hs += p * log(p + 1e-10);
    }
    sr[tid] = hs; __syncthreads();
    for (int o = 128; o > 0; o >>= 1) {
        if (tid < o) sr[tid] += sr[tid + o];
        __syncthreads();
    }
    if (tid == 0) dout[PERP_OFF] = (float)exp(-sr[0]);
}

// ---------------------------------------------------------------------------
extern "C" void kernel_launch(void* const* d_in, const int* in_sizes, int n_in,
                              void* d_out, int out_size) {
    const float* x   = (const float*)d_in[0];
    const float* Wl  = (const float*)d_in[1];
    const float* bl  = (const float*)d_in[2];
    const float* emb = (const float*)d_in[3];
    float* dout = (float*)d_out;

    cudaFuncSetAttribute(k_gemm, cudaFuncAttributeMaxDynamicSharedMemorySize, SMEM_GEMM);

    k_prep<<<96, 256>>>(Wl);
    k_esq<<<(KCODES*32)/256, 256>>>(emb);
    k_linear<<<BB*HH, 128>>>(x, bl);
    k_zsq<<<(NROWS*32)/256, 256>>>();
    k_gemm<<<NROWS/RM, 256, SMEM_GEMM>>>();
    k_rescore<<<NROWS/8, 256>>>(emb);
    k_output<<<BB*HH, 256>>>(emb, dout);
    k_final<<<1, 256>>>(dout);
}

// round 7
// speedup vs baseline: 3.4223x; 1.3221x over previous
#include <cuda_runtime.h>
#include <cuda_bf16.h>
#include <math.h>
#include <stdint.h>

// Problem constants
#define NROWS 32768   // B*H*W
#define CDIM  128
#define KCODES 8192
#define BB 32
#define HH 32
#define WW 32

#define RM 256        // rows per GEMM block
#define KN 128        // codes per tile
#define NT (KCODES/KN)
#define MARGIN 3.0f
#define CAP 32

// Output buffer layout: [loss(1)] [out(B*C*H*W)] [perplexity(1)] [idx(NROWS)]
#define OUT_OFF  1
#define PERP_OFF (1 + NROWS*CDIM)
#define IDX_OFF  (PERP_OFF + 1)

// Scratch (static __device__ — no allocations allowed)
__device__ __align__(256) float g_z[NROWS*CDIM];        // projected inputs [N,C] fp32
__device__ __align__(256) __nv_bfloat16 g_zbf[NROWS*CDIM];
__device__ __align__(256) __nv_bfloat16 g_ebf[KCODES*CDIM];
__device__ __align__(256) float g_zsq[NROWS];
__device__ __align__(256) float g_esq[KCODES];
__device__ __align__(256) int   g_ccnt[NROWS];          // candidate counts
__device__ __align__(256) int   g_cidx[NROWS*CAP];      // candidate indices
__device__ float g_wt[CDIM*CDIM];      // W transposed
__device__ int   g_idx[NROWS];
__device__ float g_part[1024];
__device__ unsigned int g_hist[KCODES];

// ---------------------------------------------------------------------------
// helpers
__device__ __forceinline__ void cpa16(uint32_t dst, const void* src) {
    asm volatile("cp.async.ca.shared.global [%0], [%1], 16;" :: "r"(dst), "l"(src));
}
__device__ __forceinline__ void cpa_commit() {
    asm volatile("cp.async.commit_group;" ::: "memory");
}
template <int N>
__device__ __forceinline__ void cpa_wait() {
    asm volatile("cp.async.wait_group %0;" :: "n"(N) : "memory");
}
__device__ __forceinline__ void ldsm4(uint32_t* r, uint32_t addr) {
    asm volatile("ldmatrix.sync.aligned.m8n8.x4.shared.b16 {%0,%1,%2,%3},[%4];"
                 : "=r"(r[0]), "=r"(r[1]), "=r"(r[2]), "=r"(r[3]) : "r"(addr));
}
__device__ __forceinline__ void mma16816(float* d, const uint32_t* a, const uint32_t* b) {
    asm("mma.sync.aligned.m16n8k16.row.col.f32.bf16.bf16.f32 "
        "{%0,%1,%2,%3},{%4,%5,%6,%7},{%8,%9},{%0,%1,%2,%3};"
        : "+f"(d[0]), "+f"(d[1]), "+f"(d[2]), "+f"(d[3])
        : "r"(a[0]), "r"(a[1]), "r"(a[2]), "r"(a[3]), "r"(b[0]), "r"(b[1]));
}
// monotone float<->u32 key for atomicMin on floats (incl. negatives)
__device__ __forceinline__ unsigned fkey(float f) {
    int i = __float_as_int(f);
    return (i >= 0) ? ((unsigned)i | 0x80000000u) : (unsigned)(~i);
}
__device__ __forceinline__ float finv(unsigned u) {
    int i = (u & 0x80000000u) ? (int)(u & 0x7fffffffu) : ~(int)u;
    return __int_as_float(i);
}

// ---------------------------------------------------------------------------
__global__ void k_prep(const float* __restrict__ Wl) {
    int i = blockIdx.x * 256 + threadIdx.x;
    if (i < CDIM*CDIM) {
        int j = i / CDIM, c = i % CDIM;
        g_wt[c*CDIM + j] = Wl[i];
    }
    int h = i - CDIM*CDIM;
    if (h >= 0 && h < KCODES) g_hist[h] = 0u;
}

// emb row norms + bf16 conversion. Warp per row, lane holds one float4.
__global__ void k_esq(const float* __restrict__ emb) {
    int warp = (blockIdx.x * blockDim.x + threadIdx.x) >> 5;
    int lane = threadIdx.x & 31;
    if (warp >= KCODES) return;
    float4 v = ((const float4*)(emb + (size_t)warp * CDIM))[lane];
    float s = v.x*v.x + v.y*v.y + v.z*v.z + v.w*v.w;
    #pragma unroll
    for (int o = 16; o > 0; o >>= 1) s += __shfl_xor_sync(0xffffffffu, s, o);
    if (lane == 0) g_esq[warp] = s;
    __nv_bfloat162 p0 = __floats2bfloat162_rn(v.x, v.y);
    __nv_bfloat162 p1 = __floats2bfloat162_rn(v.z, v.w);
    uint2 u; u.x = *(unsigned*)&p0; u.y = *(unsigned*)&p1;
    ((uint2*)g_ebf)[warp*32 + lane] = u;
}

// z row norms + zero candidate counts
__global__ void k_zsq() {
    int warp = (blockIdx.x * blockDim.x + threadIdx.x) >> 5;
    int lane = threadIdx.x & 31;
    if (warp >= NROWS) return;
    float4 v = ((const float4*)(g_z + (size_t)warp * CDIM))[lane];
    float s = v.x*v.x + v.y*v.y + v.z*v.z + v.w*v.w;
    #pragma unroll
    for (int o = 16; o > 0; o >>= 1) s += __shfl_xor_sync(0xffffffffu, s, o);
    if (lane == 0) { g_zsq[warp] = s; g_ccnt[warp] = 0; }
}

// ---------------------------------------------------------------------------
// Linear projection -> g_z (fp32) and g_zbf (bf16)
__global__ void k_linear(const float* __restrict__ x, const float* __restrict__ bl) {
    __shared__ float xs[CDIM*WW];
    int bh = blockIdx.x;
    int b = bh >> 5, h = bh & 31;
    int tid = threadIdx.x;          // 128
    int w = tid & 31, cg = tid >> 5;
    const float* xp = x + ((size_t)(b*CDIM) * HH + h) * WW;
    #pragma unroll
    for (int cc = 0; cc < 32; cc++) {
        int c = cg*32 + cc;
        xs[c*WW + w] = xp[(size_t)c * (HH*WW) + w];
    }
    __syncthreads();

    int j = tid;
    float bj = bl[j];
    float acc[WW];
    #pragma unroll
    for (int ww = 0; ww < WW; ww++) acc[ww] = bj;

    #pragma unroll 4
    for (int c = 0; c < CDIM; c++) {
        float wv = g_wt[c*CDIM + j];
        #pragma unroll
        for (int w4 = 0; w4 < WW/4; w4++) {
            float4 xv = *(const float4*)&xs[c*WW + w4*4];
            acc[w4*4+0] += xv.x * wv;
            acc[w4*4+1] += xv.y * wv;
            acc[w4*4+2] += xv.z * wv;
            acc[w4*4+3] += xv.w * wv;
        }
    }
    int nbase = bh * WW;
    #pragma unroll
    for (int ww = 0; ww < WW; ww++) {
        g_z[(size_t)(nbase+ww)*CDIM + j] = acc[ww];
        g_zbf[(size_t)(nbase+ww)*CDIM + j] = __float2bfloat16_rn(acc[ww]);
    }
}

// ---------------------------------------------------------------------------
// Single-pass bf16 mma.sync GEMM + running-min threshold + collection.
// Block: 256 rows x K loop (tiles of 128 codes). 512 threads = 16 warps:
// warp_m = wid&3 (64 rows), warp_n = wid>>2 (32 codes). Grid=128 -> single
// wave, 4 warps/SMSP for latency hiding.
// smem tiles bf16, 16B-chunk XOR swizzle: chunk' = chunk ^ (row&7).
// smem bytes: zt 65536 | et 2x32768 | ssq 2x512 | samin 1024
#define SMEM_GEMM (65536 + 65536 + 1024 + 1024)

__global__ void __launch_bounds__(512, 1) k_gemm() {
    extern __shared__ char smc[];
    char* zt = smc;                               // 64KB (256 rows)
    char* et = smc + 65536;                       // 2 x 32KB
    float* ssq = (float*)(smc + 131072);          // 2 x 128
    unsigned* samin = (unsigned*)(smc + 132096);  // 256 running row-min (fkey)

    int tid = threadIdx.x, lane = tid & 31, wid = tid >> 5;
    int warp_m = wid & 3, warp_n = wid >> 2;
    int rowbase = blockIdx.x * RM;

    uint32_t zt_a = (uint32_t)__cvta_generic_to_shared(zt);
    uint32_t et_a = (uint32_t)__cvta_generic_to_shared(et);
    uint32_t ssq_a = (uint32_t)__cvta_generic_to_shared(ssq);

    auto stage_e = [&](int t) {
        int buf = t & 1;
        const char* src = (const char*)g_ebf + (size_t)t * KN * 256;
        uint32_t db = et_a + (uint32_t)buf * 32768u;
        #pragma unroll
        for (int u = 0; u < 4; u++) {
            int i = u*512 + tid;
            int r = i >> 4, c = i & 15;
            cpa16(db + (uint32_t)(r*16 + (c ^ (r & 7)))*16u, src + r*256 + c*16);
        }
        if (tid < 32)
            cpa16(ssq_a + (uint32_t)buf*512u + (uint32_t)tid*16u, g_esq + t*KN + tid*4);
    };

    // prologue: z tile (256 rows) + e tile 0
    {
        const char* src = (const char*)g_zbf + (size_t)rowbase * 256;
        #pragma unroll
        for (int u = 0; u < 8; u++) {
            int i = u*512 + tid;
            int r = i >> 4, c = i & 15;
            cpa16(zt_a + (uint32_t)(r*16 + (c ^ (r & 7)))*16u, src + r*256 + c*16);
        }
        stage_e(0);
        cpa_commit();
    }
    if (tid < 256) samin[tid] = 0xFFFFFFFFu;

    // per-lane row slots: slot = mt*2 + half -> row offset in block
    int rows8[8]; float zsq8[8];
    #pragma unroll
    for (int sl = 0; sl < 8; sl++) {
        int mt = sl >> 1, half = sl & 1;
        rows8[sl] = warp_m*64 + mt*16 + (lane >> 2) + half*8;
        zsq8[sl] = g_zsq[rowbase + rows8[sl]];
    }

    // ldmatrix lane addressing constants
    int hiA = (lane >> 4) & 1;
    int hiB = (lane >> 3) & 1;
    int am7[4]; uint32_t abase[4];
    #pragma unroll
    for (int mt = 0; mt < 4; mt++) {
        int ar = warp_m*64 + mt*16 + (lane & 15);
        am7[mt] = ar & 7; abase[mt] = zt_a + (uint32_t)ar*256u;
    }
    int bm7[2]; uint32_t bbase[2];
    #pragma unroll
    for (int g = 0; g < 2; g++) {
        int br = warp_n*32 + g*16 + (lane & 7) + ((lane >> 4) << 3);
        bm7[g] = br & 7; bbase[g] = et_a + (uint32_t)br*256u;
    }

    for (int t = 0; t < NT; t++) {
        cpa_wait<0>();     // tile t staged (issued in prev iter / prologue)
        __syncthreads();   // staged visible to all; prev-iter readers done
        // prefetch next tile now: overlaps entire kloop+epilogue below.
        // Safe: buffer (t+1)&1's last readers finished before the sync above.
        if (t + 1 < NT) { stage_e(t + 1); cpa_commit(); }

        uint32_t ebb = (uint32_t)(t & 1) * 32768u;

        float acc[4][4][4];
        #pragma unroll
        for (int a = 0; a < 4; a++)
            #pragma unroll
            for (int b = 0; b < 4; b++)
                #pragma unroll
                for (int c = 0; c < 4; c++) acc[a][b][c] = 0.f;

        #pragma unroll
        for (int s = 0; s < 8; s++) {
            uint32_t Ar[4][4], Br[2][4];
            #pragma unroll
            for (int mt = 0; mt < 4; mt++) {
                uint32_t ad = abase[mt] + (uint32_t)(((2*s + hiA) ^ am7[mt]) << 4);
                ldsm4(Ar[mt], ad);
            }
            #pragma unroll
            for (int g = 0; g < 2; g++) {
                uint32_t bd = bbase[g] + ebb + (uint32_t)(((2*s + hiB) ^ bm7[g]) << 4);
                ldsm4(Br[g], bd);
            }
            #pragma unroll
            for (int mt = 0; mt < 4; mt++)
                #pragma unroll
                for (int g = 0; g < 2; g++) {
                    mma16816(acc[mt][2*g+0], Ar[mt], &Br[g][0]);
                    mma16816(acc[mt][2*g+1], Ar[mt], &Br[g][2]);
                }
        }

        // epilogue part 1: d~ = (zsq+esq) - 2*dot (in place), per-slot tile min
        const float* sq = ssq + (t & 1) * 128;
        float tmin[8];
        #pragma unroll
        for (int sl = 0; sl < 8; sl++) tmin[sl] = 3.0e38f;
        #pragma unroll
        for (int nt = 0; nt < 4; nt++) {
            int cbase = warp_n*32 + nt*8 + (lane & 3)*2;
            float2 es2 = *(const float2*)&sq[cbase];
            #pragma unroll
            for (int mt = 0; mt < 4; mt++) {
                float d0 = fmaf(-2.f, acc[mt][nt][0], zsq8[mt*2+0] + es2.x);
                float d1 = fmaf(-2.f, acc[mt][nt][1], zsq8[mt*2+0] + es2.y);
                float d2 = fmaf(-2.f, acc[mt][nt][2], zsq8[mt*2+1] + es2.x);
                float d3 = fmaf(-2.f, acc[mt][nt][3], zsq8[mt*2+1] + es2.y);
                acc[mt][nt][0] = d0; acc[mt][nt][1] = d1;
                acc[mt][nt][2] = d2; acc[mt][nt][3] = d3;
                tmin[mt*2+0] = fminf(tmin[mt*2+0], fminf(d0, d1));
                tmin[mt*2+1] = fminf(tmin[mt*2+1], fminf(d2, d3));
            }
        }
        // merge tile min into running row min (lanes 0..3 of each row group)
        #pragma unroll
        for (int sl = 0; sl < 8; sl++) {
            float v = tmin[sl];
            v = fminf(v, __shfl_xor_sync(0xffffffffu, v, 1));
            v = fminf(v, __shfl_xor_sync(0xffffffffu, v, 2));
            if ((lane & 3) == 0) atomicMin(&samin[rows8[sl]], fkey(v));
        }
        __syncthreads();   // all warps' mins merged -> thr includes tile t

        // epilogue part 2: collect candidates under running threshold
        float thr8[8];
        #pragma unroll
        for (int sl = 0; sl < 8; sl++) thr8[sl] = finv(samin[rows8[sl]]) + MARGIN;
        int kt = t * KN;
        #pragma unroll
        for (int nt = 0; nt < 4; nt++) {
            int cbase = warp_n*32 + nt*8 + (lane & 3)*2;
            #pragma unroll
            for (int mt = 0; mt < 4; mt++) {
                int r0 = rowbase + rows8[mt*2+0];
                int r1 = rowbase + rows8[mt*2+1];
                if (acc[mt][nt][0] <= thr8[mt*2+0]) {
                    int p = atomicAdd(&g_ccnt[r0], 1);
                    if (p < CAP) g_cidx[r0*CAP + p] = kt + cbase;
                }
                if (acc[mt][nt][1] <= thr8[mt*2+0]) {
                    int p = atomicAdd(&g_ccnt[r0], 1);
                    if (p < CAP) g_cidx[r0*CAP + p] = kt + cbase + 1;
                }
                if (acc[mt][nt][2] <= thr8[mt*2+1]) {
                    int p = atomicAdd(&g_ccnt[r1], 1);
                    if (p < CAP) g_cidx[r1*CAP + p] = kt + cbase;
                }
                if (acc[mt][nt][3] <= thr8[mt*2+1]) {
                    int p = atomicAdd(&g_ccnt[r1], 1);
                    if (p < CAP) g_cidx[r1*CAP + p] = kt + cbase + 1;
                }
            }
        }
        // no extra sync: next-iter top sync orders buffer reuse & samin
    }
}

// ---------------------------------------------------------------------------
// Exact fp32 rescore of candidates. Warp per row.
__global__ void k_rescore(const float* __restrict__ emb) {
    int wid = threadIdx.x >> 5, lane = threadIdx.x & 31;
    int row = blockIdx.x * 8 + wid;
    float4 z4 = ((const float4*)(g_z + (size_t)row * CDIM))[lane];
    float zs = g_zsq[row];
    int cnt = g_ccnt[row];
    float best = 3.0e38f; int bidx = 0x7fffffff;
    if (cnt <= CAP) {
        for (int c = 0; c < cnt; c++) {
            int idx = g_cidx[row*CAP + c];
            float4 e4 = ((const float4*)(emb + (size_t)idx * CDIM))[lane];
            float p = fmaf(z4.x, e4.x, fmaf(z4.y, e4.y, fmaf(z4.z, e4.z, z4.w*e4.w)));
            #pragma unroll
            for (int o = 16; o > 0; o >>= 1) p += __shfl_xor_sync(0xffffffffu, p, o);
            float d = __fsub_rn(__fadd_rn(zs, g_esq[idx]), __fmul_rn(2.0f, p));
            if (d < best || (d == best && idx < bidx)) { best = d; bidx = idx; }
        }
    } else {
        for (int idx = 0; idx < KCODES; idx++) {
            float4 e4 = ((const float4*)(emb + (size_t)idx * CDIM))[lane];
            float p = fmaf(z4.x, e4.x, fmaf(z4.y, e4.y, fmaf(z4.z, e4.z, z4.w*e4.w)));
            #pragma unroll
            for (int o = 16; o > 0; o >>= 1) p += __shfl_xor_sync(0xffffffffu, p, o);
            float d = __fsub_rn(__fadd_rn(zs, g_esq[idx]), __fmul_rn(2.0f, p));
            if (d < best) { best = d; bidx = idx; }
        }
    }
    if (lane == 0) g_idx[row] = bidx;
}

// ---------------------------------------------------------------------------
// Gather + BCHW output + SSE partials + histogram + idx output.
__global__ void k_output(const float* __restrict__ emb, float* __restrict__ dout) {
    __shared__ float se[CDIM*(WW+1)];
    __shared__ float sz[CDIM*(WW+1)];
    __shared__ int   sidx[WW];
    __shared__ float sred[8];
    int bh = blockIdx.x;
    int b = bh >> 5, h = bh & 31;
    int nbase = bh * WW;
    int tid = threadIdx.x;   // 256

    if (tid < WW) {
        int id = g_idx[nbase + tid];
        sidx[tid] = id;
        atomicAdd(&g_hist[id], 1u);
        dout[IDX_OFF + nbase + tid] = (float)id;
    }
    __syncthreads();

    for (int e = tid; e < WW*CDIM; e += 256) {
        int w = e >> 7, c = e & 127;
        se[c*(WW+1) + w] = emb[(size_t)sidx[w]*CDIM + c];
        sz[c*(WW+1) + w] = g_z[(size_t)(nbase+w)*CDIM + c];
    }
    __syncthreads();

    float lsse = 0.f;
    for (int e = tid; e < CDIM*WW; e += 256) {
        int c = e >> 5, w = e & 31;
        float q  = se[c*(WW+1) + w];
        float zz = sz[c*(WW+1) + w];
        float df = q - zz;
        lsse += df*df;
        dout[OUT_OFF + (((size_t)(b*CDIM + c))*HH + h)*WW + w] = q;
    }
    #pragma unroll
    for (int o = 16; o > 0; o >>= 1) lsse += __shfl_xor_sync(0xffffffffu, lsse, o);
    if ((tid & 31) == 0) sred[tid >> 5] = lsse;
    __syncthreads();
    if (tid == 0) {
        float s = 0.f;
        #pragma unroll
        for (int i = 0; i < 8; i++) s += sred[i];
        g_part[bh] = s;
    }
}

// ---------------------------------------------------------------------------
__global__ void k_final(float* __restrict__ dout) {
    __shared__ double sr[256];
    int tid = threadIdx.x;
    double s = 0.0;
    for (int i = tid; i < 1024; i += 256) s += (double)g_part[i];
    sr[tid] = s; __syncthreads();
    for (int o = 128; o > 0; o >>= 1) {
        if (tid < o) sr[tid] += sr[tid + o];
        __syncthreads();
    }
    if (tid == 0) {
        double mse = sr[0] / (double)(NROWS*CDIM);
        dout[0] = (float)(1.25 * mse);
    }
    __syncthreads();
    double hs = 0.0;
    for (int k = tid; k < KCODES; k += 256) {
        double p = (double)g_hist[k] / (double)NROWS;
        hs += p * log(p + 1e-10);
    }
    sr[tid] = hs; __syncthreads();
    for (int o = 128; o > 0; o >>= 1) {
        if (tid < o) sr[tid] += sr[tid + o];
        __syncthreads();
    }
    if (tid == 0) dout[PERP_OFF] = (float)exp(-sr[0]);
}

// ---------------------------------------------------------------------------
extern "C" void kernel_launch(void* const* d_in, const int* in_sizes, int n_in,
                              void* d_out, int out_size) {
    const float* x   = (const float*)d_in[0];
    const float* Wl  = (const float*)d_in[1];
    const float* bl  = (const float*)d_in[2];
    const float* emb = (const float*)d_in[3];
    float* dout = (float*)d_out;

    cudaFuncSetAttribute(k_gemm, cudaFuncAttributeMaxDynamicSharedMemorySize, SMEM_GEMM);

    k_prep<<<96, 256>>>(Wl);
    k_esq<<<(KCODES*32)/256, 256>>>(emb);
    k_linear<<<BB*HH, 128>>>(x, bl);
    k_zsq<<<(NROWS*32)/256, 256>>>();
    k_gemm<<<NROWS/RM, 512, SMEM_GEMM>>>();
    k_rescore<<<NROWS/8, 256>>>(emb);
    k_output<<<BB*HH, 256>>>(emb, dout);
    k_final<<<1, 256>>>(dout);
}

// round 8
// speedup vs baseline: 3.7069x; 1.0832x over previous
#include <cuda_runtime.h>
#include <cuda_bf16.h>
#include <math.h>
#include <stdint.h>

// Problem constants
#define NROWS 32768   // B*H*W
#define CDIM  128
#define KCODES 8192
#define BB 32
#define HH 32
#define WW 32

#define RM 256        // rows per GEMM block
#define KN 256        // codes per outer tile (2 sub-tiles of 128)
#define NTT (KCODES/KN)   // 32 outer tiles
#define MARGIN 3.0f
#define CAP 32

// Output buffer layout: [loss(1)] [out(B*C*H*W)] [perplexity(1)] [idx(NROWS)]
#define OUT_OFF  1
#define PERP_OFF (1 + NROWS*CDIM)
#define IDX_OFF  (PERP_OFF + 1)

// Scratch (static __device__ — no allocations allowed)
__device__ __align__(256) float g_z[NROWS*CDIM];        // projected inputs [N,C] fp32
__device__ __align__(256) __nv_bfloat16 g_zbf[NROWS*CDIM];
__device__ __align__(256) __nv_bfloat16 g_ebf[KCODES*CDIM];
__device__ __align__(256) float g_zsq[NROWS];
__device__ __align__(256) float g_esq[KCODES];
__device__ __align__(256) int   g_ccnt[NROWS];          // candidate counts
__device__ __align__(256) int   g_cidx[NROWS*CAP];      // candidate indices
__device__ float g_wt[CDIM*CDIM];      // W transposed
__device__ int   g_idx[NROWS];
__device__ float g_part[1024];
__device__ unsigned int g_hist[KCODES];

// ---------------------------------------------------------------------------
// helpers
__device__ __forceinline__ void cpa16(uint32_t dst, const void* src) {
    asm volatile("cp.async.ca.shared.global [%0], [%1], 16;" :: "r"(dst), "l"(src));
}
__device__ __forceinline__ void cpa_commit() {
    asm volatile("cp.async.commit_group;" ::: "memory");
}
template <int N>
__device__ __forceinline__ void cpa_wait() {
    asm volatile("cp.async.wait_group %0;" :: "n"(N) : "memory");
}
__device__ __forceinline__ void ldsm4(uint32_t* r, uint32_t addr) {
    asm volatile("ldmatrix.sync.aligned.m8n8.x4.shared.b16 {%0,%1,%2,%3},[%4];"
                 : "=r"(r[0]), "=r"(r[1]), "=r"(r[2]), "=r"(r[3]) : "r"(addr));
}
__device__ __forceinline__ void mma16816(float* d, const uint32_t* a, const uint32_t* b) {
    asm("mma.sync.aligned.m16n8k16.row.col.f32.bf16.bf16.f32 "
        "{%0,%1,%2,%3},{%4,%5,%6,%7},{%8,%9},{%0,%1,%2,%3};"
        : "+f"(d[0]), "+f"(d[1]), "+f"(d[2]), "+f"(d[3])
        : "r"(a[0]), "r"(a[1]), "r"(a[2]), "r"(a[3]), "r"(b[0]), "r"(b[1]));
}
// monotone float<->u32 key for atomicMin on floats (incl. negatives)
__device__ __forceinline__ unsigned fkey(float f) {
    int i = __float_as_int(f);
    return (i >= 0) ? ((unsigned)i | 0x80000000u) : (unsigned)(~i);
}
__device__ __forceinline__ float finv(unsigned u) {
    int i = (u & 0x80000000u) ? (int)(u & 0x7fffffffu) : ~(int)u;
    return __int_as_float(i);
}

// ---------------------------------------------------------------------------
// emb row norms + bf16 conversion + (fused) W transpose + hist zero.
// Warp per emb row, lane holds one float4.
__global__ void k_esq(const float* __restrict__ emb, const float* __restrict__ Wl) {
    int gtid = blockIdx.x * blockDim.x + threadIdx.x;
    if (gtid < CDIM*CDIM) {
        int j = gtid / CDIM, c = gtid % CDIM;
        g_wt[c*CDIM + j] = Wl[gtid];
    }
    if (gtid < KCODES) g_hist[gtid] = 0u;

    int warp = gtid >> 5;
    int lane = threadIdx.x & 31;
    if (warp >= KCODES) return;
    float4 v = ((const float4*)(emb + (size_t)warp * CDIM))[lane];
    float s = v.x*v.x + v.y*v.y + v.z*v.z + v.w*v.w;
    #pragma unroll
    for (int o = 16; o > 0; o >>= 1) s += __shfl_xor_sync(0xffffffffu, s, o);
    if (lane == 0) g_esq[warp] = s;
    __nv_bfloat162 p0 = __floats2bfloat162_rn(v.x, v.y);
    __nv_bfloat162 p1 = __floats2bfloat162_rn(v.z, v.w);
    uint2 u; u.x = *(unsigned*)&p0; u.y = *(unsigned*)&p1;
    ((uint2*)g_ebf)[warp*32 + lane] = u;
}

// z row norms + zero candidate counts
__global__ void k_zsq() {
    int warp = (blockIdx.x * blockDim.x + threadIdx.x) >> 5;
    int lane = threadIdx.x & 31;
    if (warp >= NROWS) return;
    float4 v = ((const float4*)(g_z + (size_t)warp * CDIM))[lane];
    float s = v.x*v.x + v.y*v.y + v.z*v.z + v.w*v.w;
    #pragma unroll
    for (int o = 16; o > 0; o >>= 1) s += __shfl_xor_sync(0xffffffffu, s, o);
    if (lane == 0) { g_zsq[warp] = s; g_ccnt[warp] = 0; }
}

// ---------------------------------------------------------------------------
// Linear projection -> g_z (fp32) and g_zbf (bf16)
__global__ void k_linear(const float* __restrict__ x, const float* __restrict__ bl) {
    __shared__ float xs[CDIM*WW];
    int bh = blockIdx.x;
    int b = bh >> 5, h = bh & 31;
    int tid = threadIdx.x;          // 128
    int w = tid & 31, cg = tid >> 5;
    const float* xp = x + ((size_t)(b*CDIM) * HH + h) * WW;
    #pragma unroll
    for (int cc = 0; cc < 32; cc++) {
        int c = cg*32 + cc;
        xs[c*WW + w] = xp[(size_t)c * (HH*WW) + w];
    }
    __syncthreads();

    int j = tid;
    float bj = bl[j];
    float acc[WW];
    #pragma unroll
    for (int ww = 0; ww < WW; ww++) acc[ww] = bj;

    #pragma unroll 4
    for (int c = 0; c < CDIM; c++) {
        float wv = g_wt[c*CDIM + j];
        #pragma unroll
        for (int w4 = 0; w4 < WW/4; w4++) {
            float4 xv = *(const float4*)&xs[c*WW + w4*4];
            acc[w4*4+0] += xv.x * wv;
            acc[w4*4+1] += xv.y * wv;
            acc[w4*4+2] += xv.z * wv;
            acc[w4*4+3] += xv.w * wv;
        }
    }
    int nbase = bh * WW;
    #pragma unroll
    for (int ww = 0; ww < WW; ww++) {
        g_z[(size_t)(nbase+ww)*CDIM + j] = acc[ww];
        g_zbf[(size_t)(nbase+ww)*CDIM + j] = __float2bfloat16_rn(acc[ww]);
    }
}

// ---------------------------------------------------------------------------
// Single-pass bf16 mma.sync GEMM + running-min threshold + collection.
// Block: 256 rows. Outer loop: 32 tiles of 256 codes (2 sub-tiles of 128).
// 512 threads = 16 warps: warp_m = wid&3 (64 rows), warp_n = wid>>2 (32 codes
// within each 128-code sub-tile). Grid=128 -> single wave, 4 warps/SMSP.
// One __syncthreads per outer tile. Collection threshold is read WITHOUT a
// post-merge barrier: any partially merged running min >= final min, so
// thr = partial_min + MARGIN stays a guaranteed superset threshold (only
// overcollects). Tile 0 sub 0 syncs once so thr != +inf.
// smem bytes: zt 65536 | et 2x65536 | ssq 2x1024 | samin 1024
#define SMEM_GEMM (65536 + 131072 + 2048 + 1024)

__global__ void __launch_bounds__(512, 1) k_gemm() {
    extern __shared__ char smc[];
    char* zt = smc;                               // 64KB (256 rows)
    char* et = smc + 65536;                       // 2 x 64KB (256 codes each)
    float* ssq = (float*)(smc + 196608);          // 2 x 256
    unsigned* samin = (unsigned*)(smc + 198656);  // 256 running row-min (fkey)

    int tid = threadIdx.x, lane = tid & 31, wid = tid >> 5;
    int warp_m = wid & 3, warp_n = wid >> 2;
    int rowbase = blockIdx.x * RM;

    uint32_t zt_a = (uint32_t)__cvta_generic_to_shared(zt);
    uint32_t et_a = (uint32_t)__cvta_generic_to_shared(et);
    uint32_t ssq_a = (uint32_t)__cvta_generic_to_shared(ssq);

    auto stage_e = [&](int t) {
        int buf = t & 1;
        const char* src = (const char*)g_ebf + (size_t)t * KN * 256;
        uint32_t db = et_a + (uint32_t)buf * 65536u;
        #pragma unroll
        for (int u = 0; u < 8; u++) {
            int i = u*512 + tid;
            int r = i >> 4, c = i & 15;
            cpa16(db + (uint32_t)(r*16 + (c ^ (r & 7)))*16u, src + r*256 + c*16);
        }
        if (tid < 64)
            cpa16(ssq_a + (uint32_t)buf*1024u + (uint32_t)tid*16u, g_esq + t*KN + tid*4);
    };

    // prologue: z tile (256 rows) + e tile 0
    {
        const char* src = (const char*)g_zbf + (size_t)rowbase * 256;
        #pragma unroll
        for (int u = 0; u < 8; u++) {
            int i = u*512 + tid;
            int r = i >> 4, c = i & 15;
            cpa16(zt_a + (uint32_t)(r*16 + (c ^ (r & 7)))*16u, src + r*256 + c*16);
        }
        stage_e(0);
        cpa_commit();
    }
    if (tid < 256) samin[tid] = 0xFFFFFFFFu;

    // per-lane row slots: slot = mt*2 + half -> row offset in block
    int rows8[8]; float zsq8[8];
    #pragma unroll
    for (int sl = 0; sl < 8; sl++) {
        int mt = sl >> 1, half = sl & 1;
        rows8[sl] = warp_m*64 + mt*16 + (lane >> 2) + half*8;
        zsq8[sl] = g_zsq[rowbase + rows8[sl]];
    }

    // ldmatrix lane addressing constants
    int hiA = (lane >> 4) & 1;
    int hiB = (lane >> 3) & 1;
    int am7[4]; uint32_t abase[4];
    #pragma unroll
    for (int mt = 0; mt < 4; mt++) {
        int ar = warp_m*64 + mt*16 + (lane & 15);
        am7[mt] = ar & 7; abase[mt] = zt_a + (uint32_t)ar*256u;
    }
    int bm7[2]; uint32_t bbase[2];
    #pragma unroll
    for (int g = 0; g < 2; g++) {
        int br = warp_n*32 + g*16 + (lane & 7) + ((lane >> 4) << 3);
        bm7[g] = br & 7; bbase[g] = et_a + (uint32_t)br*256u;
    }

    for (int t = 0; t < NTT; t++) {
        cpa_wait<0>();     // tile t staged (issued in prev iter / prologue)
        __syncthreads();   // staged visible to all; prev-iter readers done
        // prefetch next outer tile: overlaps both sub-tiles below.
        if (t + 1 < NTT) { stage_e(t + 1); cpa_commit(); }

        #pragma unroll
        for (int sub = 0; sub < 2; sub++) {
            uint32_t ebb = (uint32_t)(t & 1) * 65536u + (uint32_t)sub * 32768u;

            float acc[4][4][4];
            #pragma unroll
            for (int a = 0; a < 4; a++)
                #pragma unroll
                for (int b = 0; b < 4; b++)
                    #pragma unroll
                    for (int c = 0; c < 4; c++) acc[a][b][c] = 0.f;

            #pragma unroll
            for (int s = 0; s < 8; s++) {
                uint32_t Ar[4][4], Br[2][4];
                #pragma unroll
                for (int mt = 0; mt < 4; mt++) {
                    uint32_t ad = abase[mt] + (uint32_t)(((2*s + hiA) ^ am7[mt]) << 4);
                    ldsm4(Ar[mt], ad);
                }
                #pragma unroll
                for (int g = 0; g < 2; g++) {
                    uint32_t bd = bbase[g] + ebb + (uint32_t)(((2*s + hiB) ^ bm7[g]) << 4);
                    ldsm4(Br[g], bd);
                }
                #pragma unroll
                for (int mt = 0; mt < 4; mt++)
                    #pragma unroll
                    for (int g = 0; g < 2; g++) {
                        mma16816(acc[mt][2*g+0], Ar[mt], &Br[g][0]);
                        mma16816(acc[mt][2*g+1], Ar[mt], &Br[g][2]);
                    }
            }

            // epilogue part 1: d~ = (zsq+esq) - 2*dot, per-slot tile min
            const float* sq = ssq + (t & 1) * 256 + sub * 128;
            float tmin[8];
            #pragma unroll
            for (int sl = 0; sl < 8; sl++) tmin[sl] = 3.0e38f;
            #pragma unroll
            for (int nt = 0; nt < 4; nt++) {
                int cbase = warp_n*32 + nt*8 + (lane & 3)*2;
                float2 es2 = *(const float2*)&sq[cbase];
                #pragma unroll
                for (int mt = 0; mt < 4; mt++) {
                    float d0 = fmaf(-2.f, acc[mt][nt][0], zsq8[mt*2+0] + es2.x);
                    float d1 = fmaf(-2.f, acc[mt][nt][1], zsq8[mt*2+0] + es2.y);
                    float d2 = fmaf(-2.f, acc[mt][nt][2], zsq8[mt*2+1] + es2.x);
                    float d3 = fmaf(-2.f, acc[mt][nt][3], zsq8[mt*2+1] + es2.y);
                    acc[mt][nt][0] = d0; acc[mt][nt][1] = d1;
                    acc[mt][nt][2] = d2; acc[mt][nt][3] = d3;
                    tmin[mt*2+0] = fminf(tmin[mt*2+0], fminf(d0, d1));
                    tmin[mt*2+1] = fminf(tmin[mt*2+1], fminf(d2, d3));
                }
            }
            // merge tile min into running row min
            #pragma unroll
            for (int sl = 0; sl < 8; sl++) {
                float v = tmin[sl];
                v = fminf(v, __shfl_xor_sync(0xffffffffu, v, 1));
                v = fminf(v, __shfl_xor_sync(0xffffffffu, v, 2));
                if ((lane & 3) == 0) atomicMin(&samin[rows8[sl]], fkey(v));
            }
            if (t == 0 && sub == 0) __syncthreads();  // first threshold publish

            // epilogue part 2: collect under (possibly partially merged)
            // running threshold — always >= final min, so superset-safe.
            float thr8[8];
            #pragma unroll
            for (int sl = 0; sl < 8; sl++) thr8[sl] = finv(samin[rows8[sl]]) + MARGIN;
            int kt = t * KN + sub * 128;
            #pragma unroll
            for (int nt = 0; nt < 4; nt++) {
                int cbase = warp_n*32 + nt*8 + (lane & 3)*2;
                #pragma unroll
                for (int mt = 0; mt < 4; mt++) {
                    int r0 = rowbase + rows8[mt*2+0];
                    int r1 = rowbase + rows8[mt*2+1];
                    if (acc[mt][nt][0] <= thr8[mt*2+0]) {
                        int p = atomicAdd(&g_ccnt[r0], 1);
                        if (p < CAP) g_cidx[r0*CAP + p] = kt + cbase;
                    }
                    if (acc[mt][nt][1] <= thr8[mt*2+0]) {
                        int p = atomicAdd(&g_ccnt[r0], 1);
                        if (p < CAP) g_cidx[r0*CAP + p] = kt + cbase + 1;
                    }
                    if (acc[mt][nt][2] <= thr8[mt*2+1]) {
                        int p = atomicAdd(&g_ccnt[r1], 1);
                        if (p < CAP) g_cidx[r1*CAP + p] = kt + cbase;
                    }
                    if (acc[mt][nt][3] <= thr8[mt*2+1]) {
                        int p = atomicAdd(&g_ccnt[r1], 1);
                        if (p < CAP) g_cidx[r1*CAP + p] = kt + cbase + 1;
                    }
                }
            }
        }
        // no extra sync: next-iter top sync orders buffer reuse
    }
}

// ---------------------------------------------------------------------------
// Exact fp32 rescore of candidates. Warp per row.
__global__ void k_rescore(const float* __restrict__ emb) {
    int wid = threadIdx.x >> 5, lane = threadIdx.x & 31;
    int row = blockIdx.x * 8 + wid;
    float4 z4 = ((const float4*)(g_z + (size_t)row * CDIM))[lane];
    float zs = g_zsq[row];
    int cnt = g_ccnt[row];
    float best = 3.0e38f; int bidx = 0x7fffffff;
    if (cnt <= CAP) {
        for (int c = 0; c < cnt; c++) {
            int idx = g_cidx[row*CAP + c];
            float4 e4 = ((const float4*)(emb + (size_t)idx * CDIM))[lane];
            float p = fmaf(z4.x, e4.x, fmaf(z4.y, e4.y, fmaf(z4.z, e4.z, z4.w*e4.w)));
            #pragma unroll
            for (int o = 16; o > 0; o >>= 1) p += __shfl_xor_sync(0xffffffffu, p, o);
            float d = __fsub_rn(__fadd_rn(zs, g_esq[idx]), __fmul_rn(2.0f, p));
            if (d < best || (d == best && idx < bidx)) { best = d; bidx = idx; }
        }
    } else {
        for (int idx = 0; idx < KCODES; idx++) {
            float4 e4 = ((const float4*)(emb + (size_t)idx * CDIM))[lane];
            float p = fmaf(z4.x, e4.x, fmaf(z4.y, e4.y, fmaf(z4.z, e4.z, z4.w*e4.w)));
            #pragma unroll
            for (int o = 16; o > 0; o >>= 1) p += __shfl_xor_sync(0xffffffffu, p, o);
            float d = __fsub_rn(__fadd_rn(zs, g_esq[idx]), __fmul_rn(2.0f, p));
            if (d < best) { best = d; bidx = idx; }
        }
    }
    if (lane == 0) g_idx[row] = bidx;
}

// ---------------------------------------------------------------------------
// Gather + BCHW output + SSE partials + histogram + idx output.
__global__ void k_output(const float* __restrict__ emb, float* __restrict__ dout) {
    __shared__ float se[CDIM*(WW+1)];
    __shared__ float sz[CDIM*(WW+1)];
    __shared__ int   sidx[WW];
    __shared__ float sred[8];
    int bh = blockIdx.x;
    int b = bh >> 5, h = bh & 31;
    int nbase = bh * WW;
    int tid = threadIdx.x;   // 256

    if (tid < WW) {
        int id = g_idx[nbase + tid];
        sidx[tid] = id;
        atomicAdd(&g_hist[id], 1u);
        dout[IDX_OFF + nbase + tid] = (float)id;
    }
    __syncthreads();

    for (int e = tid; e < WW*CDIM; e += 256) {
        int w = e >> 7, c = e & 127;
        se[c*(WW+1) + w] = emb[(size_t)sidx[w]*CDIM + c];
        sz[c*(WW+1) + w] = g_z[(size_t)(nbase+w)*CDIM + c];
    }
    __syncthreads();

    float lsse = 0.f;
    for (int e = tid; e < CDIM*WW; e += 256) {
        int c = e >> 5, w = e & 31;
        float q  = se[c*(WW+1) + w];
        float zz = sz[c*(WW+1) + w];
        float df = q - zz;
        lsse += df*df;
        dout[OUT_OFF + (((size_t)(b*CDIM + c))*HH + h)*WW + w] = q;
    }
    #pragma unroll
    for (int o = 16; o > 0; o >>= 1) lsse += __shfl_xor_sync(0xffffffffu, lsse, o);
    if ((tid & 31) == 0) sred[tid >> 5] = lsse;
    __syncthreads();
    if (tid == 0) {
        float s = 0.f;
        #pragma unroll
        for (int i = 0; i < 8; i++) s += sred[i];
        g_part[bh] = s;
    }
}

// ---------------------------------------------------------------------------
__global__ void k_final(float* __restrict__ dout) {
    __shared__ double sr[256];
    int tid = threadIdx.x;
    double s = 0.0;
    for (int i = tid; i < 1024; i += 256) s += (double)g_part[i];
    sr[tid] = s; __syncthreads();
    for (int o = 128; o > 0; o >>= 1) {
        if (tid < o) sr[tid] += sr[tid + o];
        __syncthreads();
    }
    if (tid == 0) {
        double mse = sr[0] / (double)(NROWS*CDIM);
        dout[0] = (float)(1.25 * mse);
    }
    __syncthreads();
    double hs = 0.0;
    for (int k = tid; k < KCODES; k += 256) {
        double p = (double)g_hist[k] / (double)NROWS;
        hs += p * log(p + 1e-10);
    }
    sr[tid] = hs; __syncthreads();
    for (int o = 128; o > 0; o >>= 1) {
        if (tid < o) sr[tid] += sr[tid + o];
        __syncthreads();
    }
    if (tid == 0) dout[PERP_OFF] = (float)exp(-sr[0]);
}

// ---------------------------------------------------------------------------
extern "C" void kernel_launch(void* const* d_in, const int* in_sizes, int n_in,
                              void* d_out, int out_size) {
    const float* x   = (const float*)d_in[0];
    const float* Wl  = (const float*)d_in[1];
    const float* bl  = (const float*)d_in[2];
    const float* emb = (const float*)d_in[3];
    float* dout = (float*)d_out;

    cudaFuncSetAttribute(k_gemm, cudaFuncAttributeMaxDynamicSharedMemorySize, SMEM_GEMM);

    k_esq<<<(KCODES*32)/256, 256>>>(emb, Wl);
    k_linear<<<BB*HH, 128>>>(x, bl);
    k_zsq<<<(NROWS*32)/256, 256>>>();
    k_gemm<<<NROWS/RM, 512, SMEM_GEMM>>>();
    k_rescore<<<NROWS/8, 256>>>(emb);
    k_output<<<BB*HH, 256>>>(emb, dout);
    k_final<<<1, 256>>>(dout);
}

// round 9
// speedup vs baseline: 3.7989x; 1.0248x over previous
#include <cuda_runtime.h>
#include <cuda_bf16.h>
#include <math.h>
#include <stdint.h>

// Problem constants
#define NROWS 32768   // B*H*W
#define CDIM  128
#define KCODES 8192
#define BB 32
#define HH 32
#define WW 32

#define RM 256        // rows per GEMM block
#define KN 256        // codes per outer tile (2 sub-tiles of 128)
#define NTT (KCODES/KN)   // 32 outer tiles
#define MARGIN 3.0f
#define CAP 128

// Output buffer layout: [loss(1)] [out(B*C*H*W)] [perplexity(1)] [idx(NROWS)]
#define OUT_OFF  1
#define PERP_OFF (1 + NROWS*CDIM)
#define IDX_OFF  (PERP_OFF + 1)

// Scratch (static __device__ — no allocations allowed)
__device__ __align__(256) float g_z[NROWS*CDIM];        // projected inputs [N,C] fp32
__device__ __align__(256) __nv_bfloat16 g_zbf[NROWS*CDIM];
__device__ __align__(256) __nv_bfloat16 g_ebf[KCODES*CDIM];
__device__ __align__(256) float g_zsq[NROWS];
__device__ __align__(256) float g_esq[KCODES];
__device__ __align__(256) int   g_ccnt[NROWS];          // candidate counts
__device__ __align__(256) int   g_cidx[NROWS*CAP];      // candidate indices
__device__ float g_wt[CDIM*CDIM];      // W transposed
__device__ int   g_idx[NROWS];
__device__ float g_part[1024];
__device__ unsigned int g_hist[KCODES];

// ---------------------------------------------------------------------------
// helpers
__device__ __forceinline__ void cpa16(uint32_t dst, const void* src) {
    asm volatile("cp.async.ca.shared.global [%0], [%1], 16;" :: "r"(dst), "l"(src));
}
__device__ __forceinline__ void cpa_commit() {
    asm volatile("cp.async.commit_group;" ::: "memory");
}
template <int N>
__device__ __forceinline__ void cpa_wait() {
    asm volatile("cp.async.wait_group %0;" :: "n"(N) : "memory");
}
__device__ __forceinline__ void ldsm4(uint32_t* r, uint32_t addr) {
    asm volatile("ldmatrix.sync.aligned.m8n8.x4.shared.b16 {%0,%1,%2,%3},[%4];"
                 : "=r"(r[0]), "=r"(r[1]), "=r"(r[2]), "=r"(r[3]) : "r"(addr));
}
__device__ __forceinline__ void mma16816(float* d, const uint32_t* a, const uint32_t* b) {
    asm("mma.sync.aligned.m16n8k16.row.col.f32.bf16.bf16.f32 "
        "{%0,%1,%2,%3},{%4,%5,%6,%7},{%8,%9},{%0,%1,%2,%3};"
        : "+f"(d[0]), "+f"(d[1]), "+f"(d[2]), "+f"(d[3])
        : "r"(a[0]), "r"(a[1]), "r"(a[2]), "r"(a[3]), "r"(b[0]), "r"(b[1]));
}
// monotone float<->u32 key for atomicMin on floats (incl. negatives)
__device__ __forceinline__ unsigned fkey(float f) {
    int i = __float_as_int(f);
    return (i >= 0) ? ((unsigned)i | 0x80000000u) : (unsigned)(~i);
}
__device__ __forceinline__ float finv(unsigned u) {
    int i = (u & 0x80000000u) ? (int)(u & 0x7fffffffu) : ~(int)u;
    return __int_as_float(i);
}

// ---------------------------------------------------------------------------
// emb row norms + bf16 conversion + (fused) W transpose + hist zero.
// Warp per emb row, lane holds one float4.
__global__ void k_esq(const float* __restrict__ emb, const float* __restrict__ Wl) {
    int gtid = blockIdx.x * blockDim.x + threadIdx.x;
    if (gtid < CDIM*CDIM) {
        int j = gtid / CDIM, c = gtid % CDIM;
        g_wt[c*CDIM + j] = Wl[gtid];
    }
    if (gtid < KCODES) g_hist[gtid] = 0u;

    int warp = gtid >> 5;
    int lane = threadIdx.x & 31;
    if (warp >= KCODES) return;
    float4 v = ((const float4*)(emb + (size_t)warp * CDIM))[lane];
    float s = v.x*v.x + v.y*v.y + v.z*v.z + v.w*v.w;
    #pragma unroll
    for (int o = 16; o > 0; o >>= 1) s += __shfl_xor_sync(0xffffffffu, s, o);
    if (lane == 0) g_esq[warp] = s;
    __nv_bfloat162 p0 = __floats2bfloat162_rn(v.x, v.y);
    __nv_bfloat162 p1 = __floats2bfloat162_rn(v.z, v.w);
    uint2 u; u.x = *(unsigned*)&p0; u.y = *(unsigned*)&p1;
    ((uint2*)g_ebf)[warp*32 + lane] = u;
}

// z row norms + zero candidate counts
__global__ void k_zsq() {
    int warp = (blockIdx.x * blockDim.x + threadIdx.x) >> 5;
    int lane = threadIdx.x & 31;
    if (warp >= NROWS) return;
    float4 v = ((const float4*)(g_z + (size_t)warp * CDIM))[lane];
    float s = v.x*v.x + v.y*v.y + v.z*v.z + v.w*v.w;
    #pragma unroll
    for (int o = 16; o > 0; o >>= 1) s += __shfl_xor_sync(0xffffffffu, s, o);
    if (lane == 0) { g_zsq[warp] = s; g_ccnt[warp] = 0; }
}

// ---------------------------------------------------------------------------
// Linear projection -> g_z (fp32) and g_zbf (bf16)
__global__ void k_linear(const float* __restrict__ x, const float* __restrict__ bl) {
    __shared__ float xs[CDIM*WW];
    int bh = blockIdx.x;
    int b = bh >> 5, h = bh & 31;
    int tid = threadIdx.x;          // 128
    int w = tid & 31, cg = tid >> 5;
    const float* xp = x + ((size_t)(b*CDIM) * HH + h) * WW;
    #pragma unroll
    for (int cc = 0; cc < 32; cc++) {
        int c = cg*32 + cc;
        xs[c*WW + w] = xp[(size_t)c * (HH*WW) + w];
    }
    __syncthreads();

    int j = tid;
    float bj = bl[j];
    float acc[WW];
    #pragma unroll
    for (int ww = 0; ww < WW; ww++) acc[ww] = bj;

    #pragma unroll 4
    for (int c = 0; c < CDIM; c++) {
        float wv = g_wt[c*CDIM + j];
        #pragma unroll
        for (int w4 = 0; w4 < WW/4; w4++) {
            float4 xv = *(const float4*)&xs[c*WW + w4*4];
            acc[w4*4+0] += xv.x * wv;
            acc[w4*4+1] += xv.y * wv;
            acc[w4*4+2] += xv.z * wv;
            acc[w4*4+3] += xv.w * wv;
        }
    }
    int nbase = bh * WW;
    #pragma unroll
    for (int ww = 0; ww < WW; ww++) {
        g_z[(size_t)(nbase+ww)*CDIM + j] = acc[ww];
        g_zbf[(size_t)(nbase+ww)*CDIM + j] = __float2bfloat16_rn(acc[ww]);
    }
}

// ---------------------------------------------------------------------------
// Single-pass bf16 mma.sync GEMM + running-min threshold + collection.
// Block: 256 rows. Outer loop: 32 tiles of 256 codes (2 sub-tiles of 128).
// 512 threads = 16 warps: warp_m = wid&3 (64 rows), warp_n = wid>>2.
// Grid=128 -> single wave, 4 warps/SMSP.
// Collect phase guarded by a warp-level any(tile_min <= thr): candidates
// appear in only a few tiles per row, so ~90% of collect instruction slots
// are skipped (same collected set — guard is a necessary condition).
// smem bytes: zt 65536 | et 2x65536 | ssq 2x1024 | samin 1024
#define SMEM_GEMM (65536 + 131072 + 2048 + 1024)

__global__ void __launch_bounds__(512, 1) k_gemm() {
    extern __shared__ char smc[];
    char* zt = smc;                               // 64KB (256 rows)
    char* et = smc + 65536;                       // 2 x 64KB (256 codes each)
    float* ssq = (float*)(smc + 196608);          // 2 x 256
    unsigned* samin = (unsigned*)(smc + 198656);  // 256 running row-min (fkey)

    int tid = threadIdx.x, lane = tid & 31, wid = tid >> 5;
    int warp_m = wid & 3, warp_n = wid >> 2;
    int rowbase = blockIdx.x * RM;

    uint32_t zt_a = (uint32_t)__cvta_generic_to_shared(zt);
    uint32_t et_a = (uint32_t)__cvta_generic_to_shared(et);
    uint32_t ssq_a = (uint32_t)__cvta_generic_to_shared(ssq);

    auto stage_e = [&](int t) {
        int buf = t & 1;
        const char* src = (const char*)g_ebf + (size_t)t * KN * 256;
        uint32_t db = et_a + (uint32_t)buf * 65536u;
        #pragma unroll
        for (int u = 0; u < 8; u++) {
            int i = u*512 + tid;
            int r = i >> 4, c = i & 15;
            cpa16(db + (uint32_t)(r*16 + (c ^ (r & 7)))*16u, src + r*256 + c*16);
        }
        if (tid < 64)
            cpa16(ssq_a + (uint32_t)buf*1024u + (uint32_t)tid*16u, g_esq + t*KN + tid*4);
    };

    // prologue: z tile (256 rows) + e tile 0
    {
        const char* src = (const char*)g_zbf + (size_t)rowbase * 256;
        #pragma unroll
        for (int u = 0; u < 8; u++) {
            int i = u*512 + tid;
            int r = i >> 4, c = i & 15;
            cpa16(zt_a + (uint32_t)(r*16 + (c ^ (r & 7)))*16u, src + r*256 + c*16);
        }
        stage_e(0);
        cpa_commit();
    }
    if (tid < 256) samin[tid] = 0xFFFFFFFFu;

    // per-lane row slots: slot = mt*2 + half -> row offset in block
    int rows8[8]; float zsq8[8];
    #pragma unroll
    for (int sl = 0; sl < 8; sl++) {
        int mt = sl >> 1, half = sl & 1;
        rows8[sl] = warp_m*64 + mt*16 + (lane >> 2) + half*8;
        zsq8[sl] = g_zsq[rowbase + rows8[sl]];
    }

    // ldmatrix lane addressing constants
    int hiA = (lane >> 4) & 1;
    int hiB = (lane >> 3) & 1;
    int am7[4]; uint32_t abase[4];
    #pragma unroll
    for (int mt = 0; mt < 4; mt++) {
        int ar = warp_m*64 + mt*16 + (lane & 15);
        am7[mt] = ar & 7; abase[mt] = zt_a + (uint32_t)ar*256u;
    }
    int bm7[2]; uint32_t bbase[2];
    #pragma unroll
    for (int g = 0; g < 2; g++) {
        int br = warp_n*32 + g*16 + (lane & 7) + ((lane >> 4) << 3);
        bm7[g] = br & 7; bbase[g] = et_a + (uint32_t)br*256u;
    }

    for (int t = 0; t < NTT; t++) {
        cpa_wait<0>();     // tile t staged (issued in prev iter / prologue)
        __syncthreads();   // staged visible to all; prev-iter readers done
        // prefetch next outer tile: overlaps both sub-tiles below.
        if (t + 1 < NTT) { stage_e(t + 1); cpa_commit(); }

        #pragma unroll
        for (int sub = 0; sub < 2; sub++) {
            uint32_t ebb = (uint32_t)(t & 1) * 65536u + (uint32_t)sub * 32768u;

            float acc[4][4][4];
            #pragma unroll
            for (int a = 0; a < 4; a++)
                #pragma unroll
                for (int b = 0; b < 4; b++)
                    #pragma unroll
                    for (int c = 0; c < 4; c++) acc[a][b][c] = 0.f;

            #pragma unroll
            for (int s = 0; s < 8; s++) {
                uint32_t Ar[4][4], Br[2][4];
                #pragma unroll
                for (int mt = 0; mt < 4; mt++) {
                    uint32_t ad = abase[mt] + (uint32_t)(((2*s + hiA) ^ am7[mt]) << 4);
                    ldsm4(Ar[mt], ad);
                }
                #pragma unroll
                for (int g = 0; g < 2; g++) {
                    uint32_t bd = bbase[g] + ebb + (uint32_t)(((2*s + hiB) ^ bm7[g]) << 4);
                    ldsm4(Br[g], bd);
                }
                #pragma unroll
                for (int mt = 0; mt < 4; mt++)
                    #pragma unroll
                    for (int g = 0; g < 2; g++) {
                        mma16816(acc[mt][2*g+0], Ar[mt], &Br[g][0]);
                        mma16816(acc[mt][2*g+1], Ar[mt], &Br[g][2]);
                    }
            }

            // epilogue part 1: d~ = (zsq+esq) - 2*dot, per-slot tile min
            const float* sq = ssq + (t & 1) * 256 + sub * 128;
            float tmin[8];
            #pragma unroll
            for (int sl = 0; sl < 8; sl++) tmin[sl] = 3.0e38f;
            #pragma unroll
            for (int nt = 0; nt < 4; nt++) {
                int cbase = warp_n*32 + nt*8 + (lane & 3)*2;
                float2 es2 = *(const float2*)&sq[cbase];
                #pragma unroll
                for (int mt = 0; mt < 4; mt++) {
                    float d0 = fmaf(-2.f, acc[mt][nt][0], zsq8[mt*2+0] + es2.x);
                    float d1 = fmaf(-2.f, acc[mt][nt][1], zsq8[mt*2+0] + es2.y);
                    float d2 = fmaf(-2.f, acc[mt][nt][2], zsq8[mt*2+1] + es2.x);
                    float d3 = fmaf(-2.f, acc[mt][nt][3], zsq8[mt*2+1] + es2.y);
                    acc[mt][nt][0] = d0; acc[mt][nt][1] = d1;
                    acc[mt][nt][2] = d2; acc[mt][nt][3] = d3;
                    tmin[mt*2+0] = fminf(tmin[mt*2+0], fminf(d0, d1));
                    tmin[mt*2+1] = fminf(tmin[mt*2+1], fminf(d2, d3));
                }
            }
            // merge tile min into running row min
            #pragma unroll
            for (int sl = 0; sl < 8; sl++) {
                float v = tmin[sl];
                v = fminf(v, __shfl_xor_sync(0xffffffffu, v, 1));
                v = fminf(v, __shfl_xor_sync(0xffffffffu, v, 2));
                if ((lane & 3) == 0) atomicMin(&samin[rows8[sl]], fkey(v));
            }
            if (t == 0 && sub == 0) __syncthreads();  // first threshold publish

            // epilogue part 2: collect under (possibly partially merged)
            // running threshold — always >= final min, so superset-safe.
            float thr8[8];
            unsigned anyc = 0;
            #pragma unroll
            for (int sl = 0; sl < 8; sl++) {
                thr8[sl] = finv(samin[rows8[sl]]) + MARGIN;
                anyc |= (tmin[sl] <= thr8[sl]) ? 1u : 0u;
            }
            // Guard: tmin[sl] is the min of this lane's 8 columns for that
            // row; if no slot on any lane passes, no inner condition can.
            if (__any_sync(0xffffffffu, anyc)) {
                int kt = t * KN + sub * 128;
                #pragma unroll
                for (int nt = 0; nt < 4; nt++) {
                    int cbase = warp_n*32 + nt*8 + (lane & 3)*2;
                    #pragma unroll
                    for (int mt = 0; mt < 4; mt++) {
                        int r0 = rowbase + rows8[mt*2+0];
                        int r1 = rowbase + rows8[mt*2+1];
                        if (acc[mt][nt][0] <= thr8[mt*2+0]) {
                            int p = atomicAdd(&g_ccnt[r0], 1);
                            if (p < CAP) g_cidx[r0*CAP + p] = kt + cbase;
                        }
                        if (acc[mt][nt][1] <= thr8[mt*2+0]) {
                            int p = atomicAdd(&g_ccnt[r0], 1);
                            if (p < CAP) g_cidx[r0*CAP + p] = kt + cbase + 1;
                        }
                        if (acc[mt][nt][2] <= thr8[mt*2+1]) {
                            int p = atomicAdd(&g_ccnt[r1], 1);
                            if (p < CAP) g_cidx[r1*CAP + p] = kt + cbase;
                        }
                        if (acc[mt][nt][3] <= thr8[mt*2+1]) {
                            int p = atomicAdd(&g_ccnt[r1], 1);
                            if (p < CAP) g_cidx[r1*CAP + p] = kt + cbase + 1;
                        }
                    }
                }
            }
        }
        // no extra sync: next-iter top sync orders buffer reuse
    }
}

// ---------------------------------------------------------------------------
// Exact fp32 rescore of candidates. Warp per row.
__global__ void k_rescore(const float* __restrict__ emb) {
    int wid = threadIdx.x >> 5, lane = threadIdx.x & 31;
    int row = blockIdx.x * 8 + wid;
    float4 z4 = ((const float4*)(g_z + (size_t)row * CDIM))[lane];
    float zs = g_zsq[row];
    int cnt = g_ccnt[row];
    float best = 3.0e38f; int bidx = 0x7fffffff;
    if (cnt <= CAP) {
        for (int c = 0; c < cnt; c++) {
            int idx = g_cidx[row*CAP + c];
            float4 e4 = ((const float4*)(emb + (size_t)idx * CDIM))[lane];
            float p = fmaf(z4.x, e4.x, fmaf(z4.y, e4.y, fmaf(z4.z, e4.z, z4.w*e4.w)));
            #pragma unroll
            for (int o = 16; o > 0; o >>= 1) p += __shfl_xor_sync(0xffffffffu, p, o);
            float d = __fsub_rn(__fadd_rn(zs, g_esq[idx]), __fmul_rn(2.0f, p));
            if (d < best || (d == best && idx < bidx)) { best = d; bidx = idx; }
        }
    } else {
        for (int idx = 0; idx < KCODES; idx++) {
            float4 e4 = ((const float4*)(emb + (size_t)idx * CDIM))[lane];
            float p = fmaf(z4.x, e4.x, fmaf(z4.y, e4.y, fmaf(z4.z, e4.z, z4.w*e4.w)));
            #pragma unroll
            for (int o = 16; o > 0; o >>= 1) p += __shfl_xor_sync(0xffffffffu, p, o);
            float d = __fsub_rn(__fadd_rn(zs, g_esq[idx]), __fmul_rn(2.0f, p));
            if (d < best) { best = d; bidx = idx; }
        }
    }
    if (lane == 0) g_idx[row] = bidx;
}

// ---------------------------------------------------------------------------
// Gather + BCHW output + SSE partials + histogram + idx output.
__global__ void k_output(const float* __restrict__ emb, float* __restrict__ dout) {
    __shared__ float se[CDIM*(WW+1)];
    __shared__ float sz[CDIM*(WW+1)];
    __shared__ int   sidx[WW];
    __shared__ float sred[8];
    int bh = blockIdx.x;
    int b = bh >> 5, h = bh & 31;
    int nbase = bh * WW;
    int tid = threadIdx.x;   // 256

    if (tid < WW) {
        int id = g_idx[nbase + tid];
        sidx[tid] = id;
        atomicAdd(&g_hist[id], 1u);
        dout[IDX_OFF + nbase + tid] = (float)id;
    }
    __syncthreads();

    for (int e = tid; e < WW*CDIM; e += 256) {
        int w = e >> 7, c = e & 127;
        se[c*(WW+1) + w] = emb[(size_t)sidx[w]*CDIM + c];
        sz[c*(WW+1) + w] = g_z[(size_t)(nbase+w)*CDIM + c];
    }
    __syncthreads();

    float lsse = 0.f;
    for (int e = tid; e < CDIM*WW; e += 256) {
        int c = e >> 5, w = e & 31;
        float q  = se[c*(WW+1) + w];
        float zz = sz[c*(WW+1) + w];
        float df = q - zz;
        lsse += df*df;
        dout[OUT_OFF + (((size_t)(b*CDIM + c))*HH + h)*WW + w] = q;
    }
    #pragma unroll
    for (int o = 16; o > 0; o >>= 1) lsse += __shfl_xor_sync(0xffffffffu, lsse, o);
    if ((tid & 31) == 0) sred[tid >> 5] = lsse;
    __syncthreads();
    if (tid == 0) {
        float s = 0.f;
        #pragma unroll
        for (int i = 0; i < 8; i++) s += sred[i];
        g_part[bh] = s;
    }
}

// ---------------------------------------------------------------------------
__global__ void k_final(float* __restrict__ dout) {
    __shared__ double sr[256];
    int tid = threadIdx.x;
    double s = 0.0;
    for (int i = tid; i < 1024; i += 256) s += (double)g_part[i];
    sr[tid] = s; __syncthreads();
    for (int o = 128; o > 0; o >>= 1) {
        if (tid < o) sr[tid] += sr[tid + o];
        __syncthreads();
    }
    if (tid == 0) {
        double mse = sr[0] / (double)(NROWS*CDIM);
        dout[0] = (float)(1.25 * mse);
    }
    __syncthreads();
    double hs = 0.0;
    for (int k = tid; k < KCODES; k += 256) {
        double p = (double)g_hist[k] / (double)NROWS;
        hs += p * log(p + 1e-10);
    }
    sr[tid] = hs; __syncthreads();
    for (int o = 128; o > 0; o >>= 1) {
        if (tid < o) sr[tid] += sr[tid + o];
        __syncthreads();
    }
    if (tid == 0) dout[PERP_OFF] = (float)exp(-sr[0]);
}

// ---------------------------------------------------------------------------
extern "C" void kernel_launch(void* const* d_in, const int* in_sizes, int n_in,
                              void* d_out, int out_size) {
    const float* x   = (const float*)d_in[0];
    const float* Wl  = (const float*)d_in[1];
    const float* bl  = (const float*)d_in[2];
    const float* emb = (const float*)d_in[3];
    float* dout = (float*)d_out;

    cudaFuncSetAttribute(k_gemm, cudaFuncAttributeMaxDynamicSharedMemorySize, SMEM_GEMM);

    k_esq<<<(KCODES*32)/256, 256>>>(emb, Wl);
    k_linear<<<BB*HH, 128>>>(x, bl);
    k_zsq<<<(NROWS*32)/256, 256>>>();
    k_gemm<<<NROWS/RM, 512, SMEM_GEMM>>>();
    k_rescore<<<NROWS/8, 256>>>(emb);
    k_output<<<BB*HH, 256>>>(emb, dout);
    k_final<<<1, 256>>>(dout);
}

// round 10
// speedup vs baseline: 3.9797x; 1.0476x over previous
#include <cuda_runtime.h>
#include <cuda_bf16.h>
#include <math.h>
#include <stdint.h>

// Problem constants
#define NROWS 32768   // B*H*W
#define CDIM  128
#define KCODES 8192
#define BB 32
#define HH 32
#define WW 32

#define RM 256        // rows per GEMM block
#define KN 256        // codes per outer tile (2 sub-tiles of 128)
#define NTT (KCODES/KN)   // 32 outer tiles
#define MARGIN 3.0f
#define CAP 128

// Output buffer layout: [loss(1)] [out(B*C*H*W)] [perplexity(1)] [idx(NROWS)]
#define OUT_OFF  1
#define PERP_OFF (1 + NROWS*CDIM)
#define IDX_OFF  (PERP_OFF + 1)

// Scratch (static __device__ — no allocations allowed)
__device__ __align__(256) float g_z[NROWS*CDIM];        // projected inputs [N,C] fp32
__device__ __align__(256) __nv_bfloat16 g_zbf[NROWS*CDIM];
__device__ __align__(256) __nv_bfloat16 g_ebf[KCODES*CDIM];
__device__ __align__(256) float g_zsq[NROWS];
__device__ __align__(256) float g_esq[KCODES];
__device__ __align__(256) int   g_ccnt[NROWS];          // candidate counts
__device__ __align__(256) int   g_cidx[NROWS*CAP];      // candidate indices
__device__ float g_wt[CDIM*CDIM];      // W transposed
__device__ int   g_idx[NROWS];
__device__ float g_part[1024];
__device__ unsigned int g_hist[KCODES];

// ---------------------------------------------------------------------------
// helpers
__device__ __forceinline__ void cpa16(uint32_t dst, const void* src) {
    asm volatile("cp.async.ca.shared.global [%0], [%1], 16;" :: "r"(dst), "l"(src));
}
__device__ __forceinline__ void cpa_commit() {
    asm volatile("cp.async.commit_group;" ::: "memory");
}
template <int N>
__device__ __forceinline__ void cpa_wait() {
    asm volatile("cp.async.wait_group %0;" :: "n"(N) : "memory");
}
__device__ __forceinline__ void ldsm4(uint32_t* r, uint32_t addr) {
    asm volatile("ldmatrix.sync.aligned.m8n8.x4.shared.b16 {%0,%1,%2,%3},[%4];"
                 : "=r"(r[0]), "=r"(r[1]), "=r"(r[2]), "=r"(r[3]) : "r"(addr));
}
__device__ __forceinline__ void mma16816(float* d, const uint32_t* a, const uint32_t* b) {
    asm("mma.sync.aligned.m16n8k16.row.col.f32.bf16.bf16.f32 "
        "{%0,%1,%2,%3},{%4,%5,%6,%7},{%8,%9},{%0,%1,%2,%3};"
        : "+f"(d[0]), "+f"(d[1]), "+f"(d[2]), "+f"(d[3])
        : "r"(a[0]), "r"(a[1]), "r"(a[2]), "r"(a[3]), "r"(b[0]), "r"(b[1]));
}
// monotone float<->u32 key for atomicMin on floats (incl. negatives)
__device__ __forceinline__ unsigned fkey(float f) {
    int i = __float_as_int(f);
    return (i >= 0) ? ((unsigned)i | 0x80000000u) : (unsigned)(~i);
}
__device__ __forceinline__ float finv(unsigned u) {
    int i = (u & 0x80000000u) ? (int)(u & 0x7fffffffu) : ~(int)u;
    return __int_as_float(i);
}

// ---------------------------------------------------------------------------
// emb row norms + bf16 conversion + (fused) W transpose + hist zero.
__global__ void k_esq(const float* __restrict__ emb, const float* __restrict__ Wl) {
    int gtid = blockIdx.x * blockDim.x + threadIdx.x;
    if (gtid < CDIM*CDIM) {
        int j = gtid / CDIM, c = gtid % CDIM;
        g_wt[c*CDIM + j] = Wl[gtid];
    }
    if (gtid < KCODES) g_hist[gtid] = 0u;

    int warp = gtid >> 5;
    int lane = threadIdx.x & 31;
    if (warp >= KCODES) return;
    float4 v = ((const float4*)(emb + (size_t)warp * CDIM))[lane];
    float s = v.x*v.x + v.y*v.y + v.z*v.z + v.w*v.w;
    #pragma unroll
    for (int o = 16; o > 0; o >>= 1) s += __shfl_xor_sync(0xffffffffu, s, o);
    if (lane == 0) g_esq[warp] = s;
    __nv_bfloat162 p0 = __floats2bfloat162_rn(v.x, v.y);
    __nv_bfloat162 p1 = __floats2bfloat162_rn(v.z, v.w);
    uint2 u; u.x = *(unsigned*)&p0; u.y = *(unsigned*)&p1;
    ((uint2*)g_ebf)[warp*32 + lane] = u;
}

// z row norms + zero candidate counts
__global__ void k_zsq() {
    int warp = (blockIdx.x * blockDim.x + threadIdx.x) >> 5;
    int lane = threadIdx.x & 31;
    if (warp >= NROWS) return;
    float4 v = ((const float4*)(g_z + (size_t)warp * CDIM))[lane];
    float s = v.x*v.x + v.y*v.y + v.z*v.z + v.w*v.w;
    #pragma unroll
    for (int o = 16; o > 0; o >>= 1) s += __shfl_xor_sync(0xffffffffu, s, o);
    if (lane == 0) { g_zsq[warp] = s; g_ccnt[warp] = 0; }
}

// ---------------------------------------------------------------------------
// Linear projection -> g_z (fp32) and g_zbf (bf16)
__global__ void k_linear(const float* __restrict__ x, const float* __restrict__ bl) {
    __shared__ float xs[CDIM*WW];
    int bh = blockIdx.x;
    int b = bh >> 5, h = bh & 31;
    int tid = threadIdx.x;          // 128
    int w = tid & 31, cg = tid >> 5;
    const float* xp = x + ((size_t)(b*CDIM) * HH + h) * WW;
    #pragma unroll
    for (int cc = 0; cc < 32; cc++) {
        int c = cg*32 + cc;
        xs[c*WW + w] = xp[(size_t)c * (HH*WW) + w];
    }
    __syncthreads();

    int j = tid;
    float bj = bl[j];
    float acc[WW];
    #pragma unroll
    for (int ww = 0; ww < WW; ww++) acc[ww] = bj;

    #pragma unroll 4
    for (int c = 0; c < CDIM; c++) {
        float wv = g_wt[c*CDIM + j];
        #pragma unroll
        for (int w4 = 0; w4 < WW/4; w4++) {
            float4 xv = *(const float4*)&xs[c*WW + w4*4];
            acc[w4*4+0] += xv.x * wv;
            acc[w4*4+1] += xv.y * wv;
            acc[w4*4+2] += xv.z * wv;
            acc[w4*4+3] += xv.w * wv;
        }
    }
    int nbase = bh * WW;
    #pragma unroll
    for (int ww = 0; ww < WW; ww++) {
        g_z[(size_t)(nbase+ww)*CDIM + j] = acc[ww];
        g_zbf[(size_t)(nbase+ww)*CDIM + j] = __float2bfloat16_rn(acc[ww]);
    }
}

// ---------------------------------------------------------------------------
// Single-pass bf16 mma.sync GEMM + running-min threshold + collection.
// Block: 256 rows. Outer loop: 32 tiles of 256 codes (2 sub-tiles of 128).
// 1024 threads = 32 warps: warp_m = wid&7 (32 rows), warp_n = wid>>3
// (32 codes within each 128-code sub-tile). Grid=128 -> single wave,
// 8 warps/SMSP (2x round-9 occupancy; the profile showed issue=30%,
// tensor=33% with 4 warps/SMSP -> warp-starved, not throughput-bound).
// Per-warp tile halved: acc[2][4][4] = 32 regs to fit the 64-reg budget.
// smem bytes: zt 65536 | et 2x65536 | ssq 2x1024 | samin 1024
#define SMEM_GEMM (65536 + 131072 + 2048 + 1024)

__global__ void __launch_bounds__(1024, 1) k_gemm() {
    extern __shared__ char smc[];
    char* zt = smc;                               // 64KB (256 rows)
    char* et = smc + 65536;                       // 2 x 64KB (256 codes each)
    float* ssq = (float*)(smc + 196608);          // 2 x 256
    unsigned* samin = (unsigned*)(smc + 198656);  // 256 running row-min (fkey)

    int tid = threadIdx.x, lane = tid & 31, wid = tid >> 5;
    int warp_m = wid & 7, warp_n = wid >> 3;
    int rowbase = blockIdx.x * RM;

    uint32_t zt_a = (uint32_t)__cvta_generic_to_shared(zt);
    uint32_t et_a = (uint32_t)__cvta_generic_to_shared(et);
    uint32_t ssq_a = (uint32_t)__cvta_generic_to_shared(ssq);

    auto stage_e = [&](int t) {
        int buf = t & 1;
        const char* src = (const char*)g_ebf + (size_t)t * KN * 256;
        uint32_t db = et_a + (uint32_t)buf * 65536u;
        #pragma unroll
        for (int u = 0; u < 4; u++) {
            int i = u*1024 + tid;
            int r = i >> 4, c = i & 15;
            cpa16(db + (uint32_t)(r*16 + (c ^ (r & 7)))*16u, src + r*256 + c*16);
        }
        if (tid < 64)
            cpa16(ssq_a + (uint32_t)buf*1024u + (uint32_t)tid*16u, g_esq + t*KN + tid*4);
    };

    // prologue: z tile (256 rows) + e tile 0
    {
        const char* src = (const char*)g_zbf + (size_t)rowbase * 256;
        #pragma unroll
        for (int u = 0; u < 4; u++) {
            int i = u*1024 + tid;
            int r = i >> 4, c = i & 15;
            cpa16(zt_a + (uint32_t)(r*16 + (c ^ (r & 7)))*16u, src + r*256 + c*16);
        }
        stage_e(0);
        cpa_commit();
    }
    if (tid < 256) samin[tid] = 0xFFFFFFFFu;

    // per-lane row slots: slot = mt*2 + half -> row offset in block
    int rows4[4]; float zsq4[4];
    #pragma unroll
    for (int sl = 0; sl < 4; sl++) {
        int mt = sl >> 1, half = sl & 1;
        rows4[sl] = warp_m*32 + mt*16 + (lane >> 2) + half*8;
        zsq4[sl] = g_zsq[rowbase + rows4[sl]];
    }

    // ldmatrix lane addressing constants
    int hiA = (lane >> 4) & 1;
    int hiB = (lane >> 3) & 1;
    int am7[2]; uint32_t abase[2];
    #pragma unroll
    for (int mt = 0; mt < 2; mt++) {
        int ar = warp_m*32 + mt*16 + (lane & 15);
        am7[mt] = ar & 7; abase[mt] = zt_a + (uint32_t)ar*256u;
    }
    int bm7[2]; uint32_t bbase[2];
    #pragma unroll
    for (int g = 0; g < 2; g++) {
        int br = warp_n*32 + g*16 + (lane & 7) + ((lane >> 4) << 3);
        bm7[g] = br & 7; bbase[g] = et_a + (uint32_t)br*256u;
    }

    for (int t = 0; t < NTT; t++) {
        cpa_wait<0>();     // tile t staged (issued in prev iter / prologue)
        __syncthreads();   // staged visible to all; prev-iter readers done
        // prefetch next outer tile: overlaps both sub-tiles below.
        if (t + 1 < NTT) { stage_e(t + 1); cpa_commit(); }

        #pragma unroll
        for (int sub = 0; sub < 2; sub++) {
            uint32_t ebb = (uint32_t)(t & 1) * 65536u + (uint32_t)sub * 32768u;

            float acc[2][4][4];
            #pragma unroll
            for (int a = 0; a < 2; a++)
                #pragma unroll
                for (int b = 0; b < 4; b++)
                    #pragma unroll
                    for (int c = 0; c < 4; c++) acc[a][b][c] = 0.f;

            #pragma unroll
            for (int s = 0; s < 8; s++) {
                uint32_t Ar[2][4], Br[2][4];
                #pragma unroll
                for (int mt = 0; mt < 2; mt++) {
                    uint32_t ad = abase[mt] + (uint32_t)(((2*s + hiA) ^ am7[mt]) << 4);
                    ldsm4(Ar[mt], ad);
                }
                #pragma unroll
                for (int g = 0; g < 2; g++) {
                    uint32_t bd = bbase[g] + ebb + (uint32_t)(((2*s + hiB) ^ bm7[g]) << 4);
                    ldsm4(Br[g], bd);
                }
                #pragma unroll
                for (int mt = 0; mt < 2; mt++)
                    #pragma unroll
                    for (int g = 0; g < 2; g++) {
                        mma16816(acc[mt][2*g+0], Ar[mt], &Br[g][0]);
                        mma16816(acc[mt][2*g+1], Ar[mt], &Br[g][2]);
                    }
            }

            // epilogue part 1: d~ = (zsq+esq) - 2*dot, per-slot tile min
            const float* sq = ssq + (t & 1) * 256 + sub * 128;
            float tmin[4];
            #pragma unroll
            for (int sl = 0; sl < 4; sl++) tmin[sl] = 3.0e38f;
            #pragma unroll
            for (int nt = 0; nt < 4; nt++) {
                int cbase = warp_n*32 + nt*8 + (lane & 3)*2;
                float2 es2 = *(const float2*)&sq[cbase];
                #pragma unroll
                for (int mt = 0; mt < 2; mt++) {
                    float d0 = fmaf(-2.f, acc[mt][nt][0], zsq4[mt*2+0] + es2.x);
                    float d1 = fmaf(-2.f, acc[mt][nt][1], zsq4[mt*2+0] + es2.y);
                    float d2 = fmaf(-2.f, acc[mt][nt][2], zsq4[mt*2+1] + es2.x);
                    float d3 = fmaf(-2.f, acc[mt][nt][3], zsq4[mt*2+1] + es2.y);
                    acc[mt][nt][0] = d0; acc[mt][nt][1] = d1;
                    acc[mt][nt][2] = d2; acc[mt][nt][3] = d3;
                    tmin[mt*2+0] = fminf(tmin[mt*2+0], fminf(d0, d1));
                    tmin[mt*2+1] = fminf(tmin[mt*2+1], fminf(d2, d3));
                }
            }
            // merge tile min into running row min
            #pragma unroll
            for (int sl = 0; sl < 4; sl++) {
                float v = tmin[sl];
                v = fminf(v, __shfl_xor_sync(0xffffffffu, v, 1));
                v = fminf(v, __shfl_xor_sync(0xffffffffu, v, 2));
                if ((lane & 3) == 0) atomicMin(&samin[rows4[sl]], fkey(v));
            }
            if (t == 0 && sub == 0) __syncthreads();  // first threshold publish

            // epilogue part 2: collect under (possibly partially merged)
            // running threshold — always >= final min, so superset-safe.
            float thr4[4];
            unsigned anyc = 0;
            #pragma unroll
            for (int sl = 0; sl < 4; sl++) {
                thr4[sl] = finv(samin[rows4[sl]]) + MARGIN;
                anyc |= (tmin[sl] <= thr4[sl]) ? 1u : 0u;
            }
            if (__any_sync(0xffffffffu, anyc)) {
                int kt = t * KN + sub * 128;
                #pragma unroll
                for (int nt = 0; nt < 4; nt++) {
                    int cbase = warp_n*32 + nt*8 + (lane & 3)*2;
                    #pragma unroll
                    for (int mt = 0; mt < 2; mt++) {
                        int r0 = rowbase + rows4[mt*2+0];
                        int r1 = rowbase + rows4[mt*2+1];
                        if (acc[mt][nt][0] <= thr4[mt*2+0]) {
                            int p = atomicAdd(&g_ccnt[r0], 1);
                            if (p < CAP) g_cidx[r0*CAP + p] = kt + cbase;
                        }
                        if (acc[mt][nt][1] <= thr4[mt*2+0]) {
                            int p = atomicAdd(&g_ccnt[r0], 1);
                            if (p < CAP) g_cidx[r0*CAP + p] = kt + cbase + 1;
                        }
                        if (acc[mt][nt][2] <= thr4[mt*2+1]) {
                            int p = atomicAdd(&g_ccnt[r1], 1);
                            if (p < CAP) g_cidx[r1*CAP + p] = kt + cbase;
                        }
                        if (acc[mt][nt][3] <= thr4[mt*2+1]) {
                            int p = atomicAdd(&g_ccnt[r1], 1);
                            if (p < CAP) g_cidx[r1*CAP + p] = kt + cbase + 1;
                        }
                    }
                }
            }
        }
        // no extra sync: next-iter top sync orders buffer reuse
    }
}

// ---------------------------------------------------------------------------
// Exact fp32 rescore of candidates. Warp per row.
__global__ void k_rescore(const float* __restrict__ emb) {
    int wid = threadIdx.x >> 5, lane = threadIdx.x & 31;
    int row = blockIdx.x * 8 + wid;
    float4 z4 = ((const float4*)(g_z + (size_t)row * CDIM))[lane];
    float zs = g_zsq[row];
    int cnt = g_ccnt[row];
    float best = 3.0e38f; int bidx = 0x7fffffff;
    if (cnt <= CAP) {
        for (int c = 0; c < cnt; c++) {
            int idx = g_cidx[row*CAP + c];
            float4 e4 = ((const float4*)(emb + (size_t)idx * CDIM))[lane];
            float p = fmaf(z4.x, e4.x, fmaf(z4.y, e4.y, fmaf(z4.z, e4.z, z4.w*e4.w)));
            #pragma unroll
            for (int o = 16; o > 0; o >>= 1) p += __shfl_xor_sync(0xffffffffu, p, o);
            float d = __fsub_rn(__fadd_rn(zs, g_esq[idx]), __fmul_rn(2.0f, p));
            if (d < best || (d == best && idx < bidx)) { best = d; bidx = idx; }
        }
    } else {
        for (int idx = 0; idx < KCODES; idx++) {
            float4 e4 = ((const float4*)(emb + (size_t)idx * CDIM))[lane];
            float p = fmaf(z4.x, e4.x, fmaf(z4.y, e4.y, fmaf(z4.z, e4.z, z4.w*e4.w)));
            #pragma unroll
            for (int o = 16; o > 0; o >>= 1) p += __shfl_xor_sync(0xffffffffu, p, o);
            float d = __fsub_rn(__fadd_rn(zs, g_esq[idx]), __fmul_rn(2.0f, p));
            if (d < best) { best = d; bidx = idx; }
        }
    }
    if (lane == 0) g_idx[row] = bidx;
}

// ---------------------------------------------------------------------------
// Gather + BCHW output + SSE partials + histogram + idx output.
__global__ void k_output(const float* __restrict__ emb, float* __restrict__ dout) {
    __shared__ float se[CDIM*(WW+1)];
    __shared__ float sz[CDIM*(WW+1)];
    __shared__ int   sidx[WW];
    __shared__ float sred[8];
    int bh = blockIdx.x;
    int b = bh >> 5, h = bh & 31;
    int nbase = bh * WW;
    int tid = threadIdx.x;   // 256

    if (tid < WW) {
        int id = g_idx[nbase + tid];
        sidx[tid] = id;
        atomicAdd(&g_hist[id], 1u);
        dout[IDX_OFF + nbase + tid] = (float)id;
    }
    __syncthreads();

    for (int e = tid; e < WW*CDIM; e += 256) {
        int w = e >> 7, c = e & 127;
        se[c*(WW+1) + w] = emb[(size_t)sidx[w]*CDIM + c];
        sz[c*(WW+1) + w] = g_z[(size_t)(nbase+w)*CDIM + c];
    }
    __syncthreads();

    float lsse = 0.f;
    for (int e = tid; e < CDIM*WW; e += 256) {
        int c = e >> 5, w = e & 31;
        float q  = se[c*(WW+1) + w];
        float zz = sz[c*(WW+1) + w];
        float df = q - zz;
        lsse += df*df;
        dout[OUT_OFF + (((size_t)(b*CDIM + c))*HH + h)*WW + w] = q;
    }
    #pragma unroll
    for (int o = 16; o > 0; o >>= 1) lsse += __shfl_xor_sync(0xffffffffu, lsse, o);
    if ((tid & 31) == 0) sred[tid >> 5] = lsse;
    __syncthreads();
    if (tid == 0) {
        float s = 0.f;
        #pragma unroll
        for (int i = 0; i < 8; i++) s += sred[i];
        g_part[bh] = s;
    }
}

// ---------------------------------------------------------------------------
__global__ void k_final(float* __restrict__ dout) {
    __shared__ double sr[256];
    int tid = threadIdx.x;
    double s = 0.0;
    for (int i = tid; i < 1024; i += 256) s += (double)g_part[i];
    sr[tid] = s; __syncthreads();
    for (int o = 128; o > 0; o >>= 1) {
        if (tid < o) sr[tid] += sr[tid + o];
        __syncthreads();
    }
    if (tid == 0) {
        double mse = sr[0] / (double)(NROWS*CDIM);
        dout[0] = (float)(1.25 * mse);
    }
    __syncthreads();
    double hs = 0.0;
    for (int k = tid; k < KCODES; k += 256) {
        double p = (double)g_hist[k] / (double)NROWS;
        hs += p * log(p + 1e-10);
    }
    sr[tid] = hs; __syncthreads();
    for (int o = 128; o > 0; o >>= 1) {
        if (tid < o) sr[tid] += sr[tid + o];
        __syncthreads();
    }
    if (tid == 0) dout[PERP_OFF] = (float)exp(-sr[0]);
}

// ---------------------------------------------------------------------------
extern "C" void kernel_launch(void* const* d_in, const int* in_sizes, int n_in,
                              void* d_out, int out_size) {
    const float* x   = (const float*)d_in[0];
    const float* Wl  = (const float*)d_in[1];
    const float* bl  = (const float*)d_in[2];
    const float* emb = (const float*)d_in[3];
    float* dout = (float*)d_out;

    cudaFuncSetAttribute(k_gemm, cudaFuncAttributeMaxDynamicSharedMemorySize, SMEM_GEMM);

    k_esq<<<(KCODES*32)/256, 256>>>(emb, Wl);
    k_linear<<<BB*HH, 128>>>(x, bl);
    k_zsq<<<(NROWS*32)/256, 256>>>();
    k_gemm<<<NROWS/RM, 1024, SMEM_GEMM>>>();
    k_rescore<<<NROWS/8, 256>>>(emb);
    k_output<<<BB*HH, 256>>>(emb, dout);
    k_final<<<1, 256>>>(dout);
}